// round 8
// baseline (speedup 1.0000x reference)
#include <cuda_runtime.h>
#include <cuda_bf16.h>
#include <math.h>

#define Bc   4
#define Pc   1024
#define Dc   512
#define Hc   8
#define DKc  64
#define HALFW 32
#define CONCAT_P (2*Pc)

#define M_PROJ (Bc * Pc)        // 4096
#define M_OUT  (Bc * CONCAT_P)  // 8192

__device__ __nv_bfloat16 g_Ahi[3 * M_PROJ * Dc];
__device__ __nv_bfloat16 g_Alo[3 * M_PROJ * Dc];
__device__ __nv_bfloat16 g_Bhi[4 * Dc * Dc];        // weights [n][k]
__device__ __nv_bfloat16 g_Blo[4 * Dc * Dc];
__device__ __nv_bfloat16 g_QKVhi[3 * M_PROJ * Dc];
__device__ __nv_bfloat16 g_QKVlo[3 * M_PROJ * Dc];
__device__ __nv_bfloat16 g_Chi[M_OUT * Dc];
__device__ __nv_bfloat16 g_Clo[M_OUT * Dc];

// ---------------------------------------------------------------------------
__device__ __forceinline__ void split_bf16(float v, __nv_bfloat16& hi, __nv_bfloat16& lo)
{
    hi = __float2bfloat16(v);
    lo = __float2bfloat16(v - __bfloat162float(hi));
}

__global__ void split_a_kernel(const float* __restrict__ s0, const float* __restrict__ s1,
                               const float* __restrict__ s2,
                               __nv_bfloat16* __restrict__ hi, __nv_bfloat16* __restrict__ lo)
{
    int z = blockIdx.z;
    const float* src = (z == 0) ? s0 : (z == 1) ? s1 : s2;
    long long base = (long long)z * M_PROJ * Dc;
    long long n4 = (long long)M_PROJ * Dc / 4;
    long long idx = (long long)blockIdx.x * blockDim.x + threadIdx.x;
    long long stride = (long long)gridDim.x * blockDim.x;
    for (long long i = idx; i < n4; i += stride) {
        float4 v = ((const float4*)src)[i];
        __nv_bfloat16 h[4], l[4];
        split_bf16(v.x, h[0], l[0]);
        split_bf16(v.y, h[1], l[1]);
        split_bf16(v.z, h[2], l[2]);
        split_bf16(v.w, h[3], l[3]);
        long long o = base + i * 4;
        *(__nv_bfloat162*)&hi[o]     = __nv_bfloat162(h[0], h[1]);
        *(__nv_bfloat162*)&hi[o + 2] = __nv_bfloat162(h[2], h[3]);
        *(__nv_bfloat162*)&lo[o]     = __nv_bfloat162(l[0], l[1]);
        *(__nv_bfloat162*)&lo[o + 2] = __nv_bfloat162(l[2], l[3]);
    }
}

__global__ void split_b_kernel(const float* __restrict__ w0, const float* __restrict__ w1,
                               const float* __restrict__ w2, const float* __restrict__ w3,
                               __nv_bfloat16* __restrict__ hi, __nv_bfloat16* __restrict__ lo)
{
    __shared__ float t[32][33];
    int z = blockIdx.z;
    const float* W = (z == 0) ? w0 : (z == 1) ? w1 : (z == 2) ? w2 : w3;
    long long base = (long long)z * Dc * Dc;
    int n0 = blockIdx.x * 32;
    int k0 = blockIdx.y * 32;
    int tx = threadIdx.x, ty = threadIdx.y;
#pragma unroll
    for (int i = 0; i < 4; i++)
        t[ty + i * 8][tx] = W[(long long)(k0 + ty + i * 8) * Dc + n0 + tx];
    __syncthreads();
#pragma unroll
    for (int i = 0; i < 4; i++) {
        float v = t[tx][ty + i * 8];
        long long o = base + (long long)(n0 + ty + i * 8) * Dc + k0 + tx;
        __nv_bfloat16 h, l;
        split_bf16(v, h, l);
        hi[o] = h;
        lo[o] = l;
    }
}

// ---------------------------------------------------------------------------
// mma / ldmatrix helpers
// ---------------------------------------------------------------------------
__device__ __forceinline__ void mma_bf16(float* d, const unsigned* a, const unsigned* b)
{
    asm volatile(
        "mma.sync.aligned.m16n8k16.row.col.f32.bf16.bf16.f32 "
        "{%0,%1,%2,%3}, {%4,%5,%6,%7}, {%8,%9}, {%0,%1,%2,%3};"
        : "+f"(d[0]), "+f"(d[1]), "+f"(d[2]), "+f"(d[3])
        : "r"(a[0]), "r"(a[1]), "r"(a[2]), "r"(a[3]), "r"(b[0]), "r"(b[1]));
}

__device__ __forceinline__ void ldmatrix_x4(unsigned* r, unsigned addr)
{
    asm volatile("ldmatrix.sync.aligned.m8n8.x4.shared.b16 {%0,%1,%2,%3}, [%4];"
        : "=r"(r[0]), "=r"(r[1]), "=r"(r[2]), "=r"(r[3]) : "r"(addr));
}

__device__ __forceinline__ void ldmatrix_x4_trans(unsigned* r, unsigned addr)
{
    asm volatile("ldmatrix.sync.aligned.m8n8.x4.trans.shared.b16 {%0,%1,%2,%3}, [%4];"
        : "=r"(r[0]), "=r"(r[1]), "=r"(r[2]), "=r"(r[3]) : "r"(addr));
}

__device__ __forceinline__ void cpasync16(void* dst_sh, const void* src)
{
    unsigned sh = (unsigned)__cvta_generic_to_shared(dst_sh);
    asm volatile("cp.async.cg.shared.global [%0], [%1], 16;\n" :: "r"(sh), "l"(src));
}

// ---------------------------------------------------------------------------
// bf16-split GEMM (unchanged from round 7)
// ---------------------------------------------------------------------------
#define GS_STRIDE 40
#define GS_TILE   (128 * GS_STRIDE)
#define GS_STAGE  (4 * GS_TILE)
#define GEMM_SMEM_BYTES (2 * GS_STAGE * 2)   // 81920

__global__ __launch_bounds__(256)
void gemm_split_kernel(const __nv_bfloat16* __restrict__ Ah, const __nv_bfloat16* __restrict__ Al,
                       long long aStrideZ,
                       const __nv_bfloat16* __restrict__ Bh, const __nv_bfloat16* __restrict__ Bl,
                       long long bStrideZ,
                       float* C, __nv_bfloat16* Chi, __nv_bfloat16* Clo, long long cStrideZ,
                       const float* b0, const float* b1, const float* b2,
                       int M)
{
    extern __shared__ __nv_bfloat16 smem[];
    int z = blockIdx.z;
    Ah += (long long)z * aStrideZ;
    Al += (long long)z * aStrideZ;
    Bh += (long long)z * bStrideZ;
    Bl += (long long)z * bStrideZ;
    const float* bias = (z == 0) ? b0 : (z == 1) ? b1 : b2;

    int tid  = threadIdx.x;
    int lane = tid & 31;
    int warp = tid >> 5;
    int wm = (warp & 1) * 64;
    int wn = (warp >> 1) * 32;
    int row0 = blockIdx.y * 128;
    int col0 = blockIdx.x * 128;

    int cp_arr[8], cp_row[8], cp_c[8];
#pragma unroll
    for (int i = 0; i < 8; i++) {
        cp_arr[i] = i >> 1;
        int idx2 = ((i & 1) << 8) + tid;
        cp_row[i] = idx2 >> 2;
        cp_c[i] = (idx2 & 3) * 8;
    }

    float acc[4][4][4];
#pragma unroll
    for (int im = 0; im < 4; im++)
#pragma unroll
        for (int in_ = 0; in_ < 4; in_++)
#pragma unroll
            for (int r = 0; r < 4; r++) acc[im][in_][r] = 0.f;

    const int nIt = Dc / 32;

    auto load_stage = [&](int it, int s) {
        __nv_bfloat16* st = smem + s * GS_STAGE;
        int k0 = it * 32;
#pragma unroll
        for (int i = 0; i < 8; i++) {
            const __nv_bfloat16* src;
            int row = cp_row[i];
            int c = cp_c[i];
            if (cp_arr[i] == 0)      src = Ah + (long long)(row0 + row) * Dc + k0 + c;
            else if (cp_arr[i] == 1) src = Al + (long long)(row0 + row) * Dc + k0 + c;
            else if (cp_arr[i] == 2) src = Bh + (long long)(col0 + row) * Dc + k0 + c;
            else                     src = Bl + (long long)(col0 + row) * Dc + k0 + c;
            cpasync16(st + cp_arr[i] * GS_TILE + row * GS_STRIDE + c, src);
        }
        asm volatile("cp.async.commit_group;\n" ::);
    };

    load_stage(0, 0);

    for (int it = 0; it < nIt; it++) {
        int buf = it & 1;
        if (it + 1 < nIt) {
            load_stage(it + 1, buf ^ 1);
            asm volatile("cp.async.wait_group 1;\n" ::);
        } else {
            asm volatile("cp.async.wait_group 0;\n" ::);
        }
        __syncthreads();

        const __nv_bfloat16* sAh = smem + buf * GS_STAGE;
        const __nv_bfloat16* sAl = sAh + GS_TILE;
        const __nv_bfloat16* sBh = sAl + GS_TILE;
        const __nv_bfloat16* sBl = sBh + GS_TILE;

#pragma unroll
        for (int kk = 0; kk < 32; kk += 16) {
            int acol = kk + 2 * (lane & 3);
            unsigned a_h[4][4], a_l[4][4];
#pragma unroll
            for (int im = 0; im < 4; im++) {
                int rbase = wm + im * 16 + (lane >> 2);
#pragma unroll
                for (int r = 0; r < 4; r++) {
                    int row = rbase + (r & 1) * 8;
                    int col = acol + (r >> 1) * 8;
                    a_h[im][r] = *(const unsigned*)&sAh[row * GS_STRIDE + col];
                    a_l[im][r] = *(const unsigned*)&sAl[row * GS_STRIDE + col];
                }
            }
            unsigned b_h[4][2], b_l[4][2];
#pragma unroll
            for (int in_ = 0; in_ < 4; in_++) {
                int nrow = wn + in_ * 8 + (lane >> 2);
#pragma unroll
                for (int r = 0; r < 2; r++) {
                    int col = acol + r * 8;
                    b_h[in_][r] = *(const unsigned*)&sBh[nrow * GS_STRIDE + col];
                    b_l[in_][r] = *(const unsigned*)&sBl[nrow * GS_STRIDE + col];
                }
            }
#pragma unroll
            for (int im = 0; im < 4; im++)
#pragma unroll
                for (int in_ = 0; in_ < 4; in_++) {
                    mma_bf16(acc[im][in_], a_h[im], b_h[in_]);
                    mma_bf16(acc[im][in_], a_h[im], b_l[in_]);
                    mma_bf16(acc[im][in_], a_l[im], b_h[in_]);
                }
        }
        __syncthreads();
    }

#pragma unroll
    for (int im = 0; im < 4; im++) {
#pragma unroll
        for (int in_ = 0; in_ < 4; in_++) {
            int row = row0 + wm + im * 16 + (lane >> 2);
            int col = col0 + wn + in_ * 8 + 2 * (lane & 3);
            float2 bv = *(const float2*)&bias[col];
            float o0 = acc[im][in_][0] + bv.x, o1 = acc[im][in_][1] + bv.y;
            float o2 = acc[im][in_][2] + bv.x, o3 = acc[im][in_][3] + bv.y;
            long long cb = (long long)z * cStrideZ;
            if (C) {
                *(float2*)&C[cb + (long long)row * Dc + col]       = make_float2(o0, o1);
                *(float2*)&C[cb + (long long)(row + 8) * Dc + col] = make_float2(o2, o3);
            } else {
                __nv_bfloat16 h0, l0, h1, l1, h2, l2, h3, l3;
                split_bf16(o0, h0, l0); split_bf16(o1, h1, l1);
                split_bf16(o2, h2, l2); split_bf16(o3, h3, l3);
                *(__nv_bfloat162*)&Chi[cb + (long long)row * Dc + col]       = __nv_bfloat162(h0, h1);
                *(__nv_bfloat162*)&Clo[cb + (long long)row * Dc + col]       = __nv_bfloat162(l0, l1);
                *(__nv_bfloat162*)&Chi[cb + (long long)(row + 8) * Dc + col] = __nv_bfloat162(h2, h3);
                *(__nv_bfloat162*)&Clo[cb + (long long)(row + 8) * Dc + col] = __nv_bfloat162(l2, l3);
            }
        }
    }
}

// ---------------------------------------------------------------------------
// Tensor-core banded attention, 92.4KB smem -> 2 CTAs/SM.
// Layout (bytes):
//   [0, 9216)        sQh (64 x 72 bf16)      } aliased by
//   [9216, 18432)    sQl                     } sPh [0,17408)
//   [18432, 36864)   sKh (128 x 72)          } sPl [17408,34816)
//   [36864, 55296)   sKl                     } (P written after S-mma + sync)
//   [55296, 73728)   sVh (128 x 72, row-major)
//   [73728, 92160)   sVl
//   [92160, 92416)   sinv (64 fp32)
// ---------------------------------------------------------------------------
#define AT_STRIDE 72
#define AP_STRIDE 136
#define O_QH 0
#define O_QL 9216
#define O_KH 18432
#define O_KL 36864
#define O_PH 0
#define O_PL 17408
#define O_VH 55296
#define O_VL 73728
#define O_SINV 92160
#define ATTN_SMEM_BYTES 92416

__global__ __launch_bounds__(256)
void attn_mma_kernel(const __nv_bfloat16* __restrict__ QKVhi,
                     const __nv_bfloat16* __restrict__ QKVlo,
                     __nv_bfloat16* __restrict__ Chi, __nv_bfloat16* __restrict__ Clo,
                     float* __restrict__ A1, float* __restrict__ A2)
{
    extern __shared__ char smraw[];
    __nv_bfloat16* sQh = (__nv_bfloat16*)(smraw + O_QH);
    __nv_bfloat16* sQl = (__nv_bfloat16*)(smraw + O_QL);
    __nv_bfloat16* sKh = (__nv_bfloat16*)(smraw + O_KH);
    __nv_bfloat16* sKl = (__nv_bfloat16*)(smraw + O_KL);
    __nv_bfloat16* sPh = (__nv_bfloat16*)(smraw + O_PH);
    __nv_bfloat16* sPl = (__nv_bfloat16*)(smraw + O_PL);
    __nv_bfloat16* sVh = (__nv_bfloat16*)(smraw + O_VH);
    __nv_bfloat16* sVl = (__nv_bfloat16*)(smraw + O_VL);
    float*         sinv = (float*)(smraw + O_SINV);
    unsigned smem_u32 = (unsigned)__cvta_generic_to_shared(smraw);

    int tid  = threadIdx.x;
    int lane = tid & 31;
    int warp = tid >> 5;
    int q0 = blockIdx.x * 64;
    int h  = blockIdx.y;
    int zz = blockIdx.z;
    int b  = zz >> 1;
    int which = zz & 1;
    int k0 = q0 - HALFW;
    const float scale = 0.125f;

    const long long plane = (long long)M_PROJ * Dc;
    const __nv_bfloat16 *Qh, *Ql, *Kh, *Kl, *Vh, *Vl;
    int rowOffset;
    float* Aout;
    if (which == 0) {
        Qh = QKVhi;           Ql = QKVlo;
        Kh = QKVhi + plane;   Kl = QKVlo + plane;
        Vh = QKVhi + 2*plane; Vl = QKVlo + 2*plane;
        rowOffset = 0;  Aout = A1;
    } else {
        Qh = QKVhi + plane;   Ql = QKVlo + plane;
        Kh = QKVhi;           Kl = QKVlo;
        Vh = QKVhi;           Vl = QKVlo;
        rowOffset = Pc; Aout = A2;
    }
    long long headBase = (long long)b * Pc * Dc + (long long)h * DKc;
    const uint4 zero4 = make_uint4(0, 0, 0, 0);

    // Q tile (64 x 64)
    for (int t = tid; t < 512; t += 256) {
        int r = t >> 3, c = (t & 7) * 8;
        long long src = headBase + (long long)(q0 + r) * Dc + c;
        *(uint4*)&sQh[r * AT_STRIDE + c] = *(const uint4*)&Qh[src];
        *(uint4*)&sQl[r * AT_STRIDE + c] = *(const uint4*)&Ql[src];
    }
    // K + V tiles (128 x 64), row-major, zero-padded edges
    for (int t = tid; t < 1024; t += 256) {
        int r = t >> 3, c = (t & 7) * 8;
        int j = k0 + r;
        uint4 kh = zero4, kl = zero4, vh = zero4, vl = zero4;
        if (j >= 0 && j < Pc) {
            long long src = headBase + (long long)j * Dc + c;
            kh = *(const uint4*)&Kh[src];
            kl = *(const uint4*)&Kl[src];
            vh = *(const uint4*)&Vh[src];
            vl = *(const uint4*)&Vl[src];
        }
        *(uint4*)&sKh[r * AT_STRIDE + c] = kh;
        *(uint4*)&sKl[r * AT_STRIDE + c] = kl;
        *(uint4*)&sVh[r * AT_STRIDE + c] = vh;
        *(uint4*)&sVl[r * AT_STRIDE + c] = vl;
    }
    __syncthreads();

    int m0 = (warp & 1) * 32;

    // ---- S = Q*K^T (m32 x n32 per warp, k64), ldmatrix fragments ----
    float sacc[2][4][4];
#pragma unroll
    for (int mi = 0; mi < 2; mi++)
#pragma unroll
        for (int ni = 0; ni < 4; ni++)
#pragma unroll
            for (int r = 0; r < 4; r++) sacc[mi][ni][r] = 0.f;
    {
        int n0w = (warp >> 1) * 32;
#pragma unroll
        for (int ks = 0; ks < 4; ks++) {
            int kc = ks * 16;
            unsigned ah[2][4], al[2][4];
#pragma unroll
            for (int mi = 0; mi < 2; mi++) {
                int row = m0 + mi * 16 + (lane & 15);
                int col = kc + 8 * (lane >> 4);
                unsigned off = (unsigned)(row * AT_STRIDE + col) * 2;
                ldmatrix_x4(ah[mi], smem_u32 + O_QH + off);
                ldmatrix_x4(al[mi], smem_u32 + O_QL + off);
            }
            unsigned bh[4][2], bl[4][2];
#pragma unroll
            for (int nt = 0; nt < 2; nt++) {
                int row = n0w + nt * 16 + (lane & 7) + 8 * (lane >> 4);
                int col = kc + 8 * ((lane >> 3) & 1);
                unsigned off = (unsigned)(row * AT_STRIDE + col) * 2;
                unsigned th[4], tl[4];
                ldmatrix_x4(th, smem_u32 + O_KH + off);
                ldmatrix_x4(tl, smem_u32 + O_KL + off);
                bh[2*nt][0] = th[0]; bh[2*nt][1] = th[1];
                bh[2*nt+1][0] = th[2]; bh[2*nt+1][1] = th[3];
                bl[2*nt][0] = tl[0]; bl[2*nt][1] = tl[1];
                bl[2*nt+1][0] = tl[2]; bl[2*nt+1][1] = tl[3];
            }
#pragma unroll
            for (int mi = 0; mi < 2; mi++)
#pragma unroll
                for (int ni = 0; ni < 4; ni++) {
                    mma_bf16(sacc[mi][ni], ah[mi], bh[ni]);
                    mma_bf16(sacc[mi][ni], ah[mi], bl[ni]);
                    mma_bf16(sacc[mi][ni], al[mi], bh[ni]);
                }
        }
    }
    __syncthreads();   // all warps done reading Q/K -> safe to alias with P

    // ---- write S as bf16 hi/lo into P buffers ----
    {
        int n0w = (warp >> 1) * 32;
#pragma unroll
        for (int mi = 0; mi < 2; mi++)
#pragma unroll
            for (int ni = 0; ni < 4; ni++) {
                int r = m0 + mi * 16 + (lane >> 2);
                int cc = n0w + ni * 8 + 2 * (lane & 3);
                __nv_bfloat16 h0, l0, h1, l1, h2, l2, h3, l3;
                split_bf16(sacc[mi][ni][0], h0, l0);
                split_bf16(sacc[mi][ni][1], h1, l1);
                split_bf16(sacc[mi][ni][2], h2, l2);
                split_bf16(sacc[mi][ni][3], h3, l3);
                *(__nv_bfloat162*)&sPh[r * AP_STRIDE + cc]       = __nv_bfloat162(h0, h1);
                *(__nv_bfloat162*)&sPl[r * AP_STRIDE + cc]       = __nv_bfloat162(l0, l1);
                *(__nv_bfloat162*)&sPh[(r + 8) * AP_STRIDE + cc] = __nv_bfloat162(h2, h3);
                *(__nv_bfloat162*)&sPl[(r + 8) * AP_STRIDE + cc] = __nv_bfloat162(l2, l3);
            }
    }
    __syncthreads();

    // ---- softmax: reconstruct s = hi+lo, overwrite with p hi/lo ----
    {
        int qi = tid >> 2;
        int p  = tid & 3;
        int i_glob = q0 + qi;
        int jlo = i_glob - HALFW; if (jlo < 0) jlo = 0;
        int jhi = i_glob + HALFW; if (jhi > Pc - 1) jhi = Pc - 1;
        int kjlo = jlo - k0;
        int kjhi = jhi - k0;
        __nv_bfloat16* ph = &sPh[qi * AP_STRIDE];
        __nv_bfloat16* pl = &sPl[qi * AP_STRIDE];
        float m = -1e30f;
#pragma unroll 8
        for (int t = 0; t < 32; t++) {
            int kj = p + 4 * t;
            if (kj >= kjlo && kj <= kjhi) {
                float s = __bfloat162float(ph[kj]) + __bfloat162float(pl[kj]);
                m = fmaxf(m, s);
            }
        }
        m = fmaxf(m, __shfl_xor_sync(0xffffffffu, m, 1));
        m = fmaxf(m, __shfl_xor_sync(0xffffffffu, m, 2));
        float sum = 0.f;
#pragma unroll 8
        for (int t = 0; t < 32; t++) {
            int kj = p + 4 * t;
            float pv = 0.f;
            if (kj >= kjlo && kj <= kjhi) {
                float s = __bfloat162float(ph[kj]) + __bfloat162float(pl[kj]);
                pv = __expf(scale * (s - m));
                sum += pv;
            }
            __nv_bfloat16 hh, ll;
            split_bf16(pv, hh, ll);
            ph[kj] = hh;
            pl[kj] = ll;
        }
        sum += __shfl_xor_sync(0xffffffffu, sum, 1);
        sum += __shfl_xor_sync(0xffffffffu, sum, 2);
        if (p == 0) sinv[qi] = 1.0f / sum;
    }
    __syncthreads();

    // ---- fused dense A write (coalesced rows, streaming stores) ----
    if (Aout) {
        int j0 = tid * 4;
        long long abase = ((long long)b * Hc + h) * Pc * (long long)Pc;
#pragma unroll 2
        for (int r = 0; r < 64; r++) {
            int i_glob = q0 + r;
            int jlo = i_glob - HALFW; if (jlo < 0) jlo = 0;
            int jhi = i_glob + HALFW; if (jhi > Pc - 1) jhi = Pc - 1;
            float inv = sinv[r];
            float4 v = make_float4(0.f, 0.f, 0.f, 0.f);
            if (j0 + 3 >= jlo && j0 <= jhi) {
                const __nv_bfloat16* ph = &sPh[r * AP_STRIDE];
                const __nv_bfloat16* pl = &sPl[r * AP_STRIDE];
                int j;
                j = j0 + 0; if (j >= jlo && j <= jhi) v.x = (__bfloat162float(ph[j-k0]) + __bfloat162float(pl[j-k0])) * inv;
                j = j0 + 1; if (j >= jlo && j <= jhi) v.y = (__bfloat162float(ph[j-k0]) + __bfloat162float(pl[j-k0])) * inv;
                j = j0 + 2; if (j >= jlo && j <= jhi) v.z = (__bfloat162float(ph[j-k0]) + __bfloat162float(pl[j-k0])) * inv;
                j = j0 + 3; if (j >= jlo && j <= jhi) v.w = (__bfloat162float(ph[j-k0]) + __bfloat162float(pl[j-k0])) * inv;
            }
            __stcs((float4*)&Aout[abase + (long long)i_glob * Pc + j0], v);
        }
    }

    // ---- O = P*V (m32 x n16 per warp, k128), ldmatrix + trans for V ----
    {
        int n0o = (warp >> 1) * 16;
        float oacc[2][2][4];
#pragma unroll
        for (int mi = 0; mi < 2; mi++)
#pragma unroll
            for (int ni = 0; ni < 2; ni++)
#pragma unroll
                for (int r = 0; r < 4; r++) oacc[mi][ni][r] = 0.f;

#pragma unroll
        for (int ks = 0; ks < 8; ks++) {
            int kc = ks * 16;
            unsigned ah[2][4], al[2][4];
#pragma unroll
            for (int mi = 0; mi < 2; mi++) {
                int row = m0 + mi * 16 + (lane & 15);
                int col = kc + 8 * (lane >> 4);
                unsigned off = (unsigned)(row * AP_STRIDE + col) * 2;
                ldmatrix_x4(ah[mi], smem_u32 + O_PH + off);
                ldmatrix_x4(al[mi], smem_u32 + O_PL + off);
            }
            unsigned bh[2][2], bl[2][2];
            {
                int row = kc + (lane & 15);
                int col = n0o + 8 * (lane >> 4);
                unsigned off = (unsigned)(row * AT_STRIDE + col) * 2;
                unsigned th[4], tl[4];
                ldmatrix_x4_trans(th, smem_u32 + O_VH + off);
                ldmatrix_x4_trans(tl, smem_u32 + O_VL + off);
                bh[0][0] = th[0]; bh[0][1] = th[1];
                bh[1][0] = th[2]; bh[1][1] = th[3];
                bl[0][0] = tl[0]; bl[0][1] = tl[1];
                bl[1][0] = tl[2]; bl[1][1] = tl[3];
            }
#pragma unroll
            for (int mi = 0; mi < 2; mi++)
#pragma unroll
                for (int ni = 0; ni < 2; ni++) {
                    mma_bf16(oacc[mi][ni], ah[mi], bh[ni]);
                    mma_bf16(oacc[mi][ni], ah[mi], bl[ni]);
                    mma_bf16(oacc[mi][ni], al[mi], bh[ni]);
                }
        }

#pragma unroll
        for (int mi = 0; mi < 2; mi++)
#pragma unroll
            for (int ni = 0; ni < 2; ni++) {
                int qi0 = m0 + mi * 16 + (lane >> 2);
                int d   = n0o + ni * 8 + 2 * (lane & 3);
                float inv0 = sinv[qi0];
                float inv1 = sinv[qi0 + 8];
                float o0 = oacc[mi][ni][0] * inv0, o1 = oacc[mi][ni][1] * inv0;
                float o2 = oacc[mi][ni][2] * inv1, o3 = oacc[mi][ni][3] * inv1;
                long long dst0 = ((long long)b * CONCAT_P + rowOffset + q0 + qi0) * Dc
                                 + h * DKc + d;
                long long dst1 = dst0 + 8LL * Dc;
                __nv_bfloat16 h0, l0, h1, l1, h2, l2, h3, l3;
                split_bf16(o0, h0, l0); split_bf16(o1, h1, l1);
                split_bf16(o2, h2, l2); split_bf16(o3, h3, l3);
                *(__nv_bfloat162*)&Chi[dst0] = __nv_bfloat162(h0, h1);
                *(__nv_bfloat162*)&Clo[dst0] = __nv_bfloat162(l0, l1);
                *(__nv_bfloat162*)&Chi[dst1] = __nv_bfloat162(h2, h3);
                *(__nv_bfloat162*)&Clo[dst1] = __nv_bfloat162(l2, l3);
            }
    }
}

// ---------------------------------------------------------------------------
extern "C" void kernel_launch(void* const* d_in, const int* in_sizes, int n_in,
                              void* d_out, int out_size)
{
    const float* queries = (const float*)d_in[0];
    const float* keys    = (const float*)d_in[1];
    const float* values  = (const float*)d_in[2];
    const float* Wq = (const float*)d_in[3];
    const float* bq = (const float*)d_in[4];
    const float* Wk = (const float*)d_in[5];
    const float* bk = (const float*)d_in[6];
    const float* Wv = (const float*)d_in[7];
    const float* bv = (const float*)d_in[8];
    const float* Wo = (const float*)d_in[9];
    const float* bo = (const float*)d_in[10];

    float* out = (float*)d_out;

    __nv_bfloat16 *Ahi, *Alo, *Bhi, *Blo, *QKVhi, *QKVlo, *Chi, *Clo;
    cudaGetSymbolAddress((void**)&Ahi, g_Ahi);
    cudaGetSymbolAddress((void**)&Alo, g_Alo);
    cudaGetSymbolAddress((void**)&Bhi, g_Bhi);
    cudaGetSymbolAddress((void**)&Blo, g_Blo);
    cudaGetSymbolAddress((void**)&QKVhi, g_QKVhi);
    cudaGetSymbolAddress((void**)&QKVlo, g_QKVlo);
    cudaGetSymbolAddress((void**)&Chi, g_Chi);
    cudaGetSymbolAddress((void**)&Clo, g_Clo);

    static int attr_set = 0;
    if (!attr_set) {
        cudaFuncSetAttribute(attn_mma_kernel,
                             cudaFuncAttributeMaxDynamicSharedMemorySize, ATTN_SMEM_BYTES);
        cudaFuncSetAttribute(gemm_split_kernel,
                             cudaFuncAttributeMaxDynamicSharedMemorySize, GEMM_SMEM_BYTES);
        attr_set = 1;
    }

    const long long mainN = (long long)M_OUT * Dc;
    const long long aN    = (long long)Bc * Hc * Pc * Pc;
    float* A1 = nullptr;
    float* A2 = nullptr;
    if ((long long)out_size >= mainN + 2 * aN) {
        A1 = out + mainN;
        A2 = A1 + aN;
    }

    split_a_kernel<<<dim3(256, 1, 3), 256>>>(queries, keys, values, Ahi, Alo);
    split_b_kernel<<<dim3(16, 16, 4), dim3(32, 8)>>>(Wq, Wk, Wv, Wo, Bhi, Blo);

    const long long aStride = (long long)M_PROJ * Dc;
    const long long bStride = (long long)Dc * Dc;

    gemm_split_kernel<<<dim3(Dc / 128, M_PROJ / 128, 3), 256, GEMM_SMEM_BYTES>>>(
        Ahi, Alo, aStride, Bhi, Blo, bStride,
        nullptr, QKVhi, QKVlo, aStride, bq, bk, bv, M_PROJ);

    dim3 ga(Pc / 64, Hc, Bc * 2);
    attn_mma_kernel<<<ga, 256, ATTN_SMEM_BYTES>>>(QKVhi, QKVlo, Chi, Clo, A1, A2);

    gemm_split_kernel<<<dim3(Dc / 128, M_OUT / 128, 1), 256, GEMM_SMEM_BYTES>>>(
        Chi, Clo, 0, Bhi + 3 * bStride, Blo + 3 * bStride, 0,
        out, nullptr, nullptr, 0, bo, bo, bo, M_OUT);
}

// round 9
// speedup vs baseline: 1.1240x; 1.1240x over previous
#include <cuda_runtime.h>
#include <cuda_bf16.h>
#include <math.h>

#define Bc   4
#define Pc   1024
#define Dc   512
#define Hc   8
#define DKc  64
#define HALFW 32
#define CONCAT_P (2*Pc)

#define M_PROJ (Bc * Pc)        // 4096
#define M_OUT  (Bc * CONCAT_P)  // 8192

__device__ __nv_bfloat16 g_Ahi[3 * M_PROJ * Dc];
__device__ __nv_bfloat16 g_Alo[3 * M_PROJ * Dc];
__device__ __nv_bfloat16 g_Bhi[4 * Dc * Dc];        // weights [n][k]
__device__ __nv_bfloat16 g_Blo[4 * Dc * Dc];
__device__ __nv_bfloat16 g_QKVhi[3 * M_PROJ * Dc];
__device__ __nv_bfloat16 g_QKVlo[3 * M_PROJ * Dc];
__device__ __nv_bfloat16 g_Chi[M_OUT * Dc];
__device__ __nv_bfloat16 g_Clo[M_OUT * Dc];

// ---------------------------------------------------------------------------
__device__ __forceinline__ void split_bf16(float v, __nv_bfloat16& hi, __nv_bfloat16& lo)
{
    hi = __float2bfloat16(v);
    lo = __float2bfloat16(v - __bfloat162float(hi));
}

__global__ void split_a_kernel(const float* __restrict__ s0, const float* __restrict__ s1,
                               const float* __restrict__ s2,
                               __nv_bfloat16* __restrict__ hi, __nv_bfloat16* __restrict__ lo)
{
    int z = blockIdx.z;
    const float* src = (z == 0) ? s0 : (z == 1) ? s1 : s2;
    long long base = (long long)z * M_PROJ * Dc;
    long long n4 = (long long)M_PROJ * Dc / 4;
    long long idx = (long long)blockIdx.x * blockDim.x + threadIdx.x;
    long long stride = (long long)gridDim.x * blockDim.x;
    for (long long i = idx; i < n4; i += stride) {
        float4 v = ((const float4*)src)[i];
        __nv_bfloat16 h[4], l[4];
        split_bf16(v.x, h[0], l[0]);
        split_bf16(v.y, h[1], l[1]);
        split_bf16(v.z, h[2], l[2]);
        split_bf16(v.w, h[3], l[3]);
        long long o = base + i * 4;
        *(__nv_bfloat162*)&hi[o]     = __nv_bfloat162(h[0], h[1]);
        *(__nv_bfloat162*)&hi[o + 2] = __nv_bfloat162(h[2], h[3]);
        *(__nv_bfloat162*)&lo[o]     = __nv_bfloat162(l[0], l[1]);
        *(__nv_bfloat162*)&lo[o + 2] = __nv_bfloat162(l[2], l[3]);
    }
}

__global__ void split_b_kernel(const float* __restrict__ w0, const float* __restrict__ w1,
                               const float* __restrict__ w2, const float* __restrict__ w3,
                               __nv_bfloat16* __restrict__ hi, __nv_bfloat16* __restrict__ lo)
{
    __shared__ float t[32][33];
    int z = blockIdx.z;
    const float* W = (z == 0) ? w0 : (z == 1) ? w1 : (z == 2) ? w2 : w3;
    long long base = (long long)z * Dc * Dc;
    int n0 = blockIdx.x * 32;
    int k0 = blockIdx.y * 32;
    int tx = threadIdx.x, ty = threadIdx.y;
#pragma unroll
    for (int i = 0; i < 4; i++)
        t[ty + i * 8][tx] = W[(long long)(k0 + ty + i * 8) * Dc + n0 + tx];
    __syncthreads();
#pragma unroll
    for (int i = 0; i < 4; i++) {
        float v = t[tx][ty + i * 8];
        long long o = base + (long long)(n0 + ty + i * 8) * Dc + k0 + tx;
        __nv_bfloat16 h, l;
        split_bf16(v, h, l);
        hi[o] = h;
        lo[o] = l;
    }
}

// ---------------------------------------------------------------------------
// mma / ldmatrix helpers
// ---------------------------------------------------------------------------
__device__ __forceinline__ void mma_bf16(float* d, const unsigned* a, const unsigned* b)
{
    asm volatile(
        "mma.sync.aligned.m16n8k16.row.col.f32.bf16.bf16.f32 "
        "{%0,%1,%2,%3}, {%4,%5,%6,%7}, {%8,%9}, {%0,%1,%2,%3};"
        : "+f"(d[0]), "+f"(d[1]), "+f"(d[2]), "+f"(d[3])
        : "r"(a[0]), "r"(a[1]), "r"(a[2]), "r"(a[3]), "r"(b[0]), "r"(b[1]));
}

__device__ __forceinline__ void ldmatrix_x4(unsigned* r, unsigned addr)
{
    asm volatile("ldmatrix.sync.aligned.m8n8.x4.shared.b16 {%0,%1,%2,%3}, [%4];"
        : "=r"(r[0]), "=r"(r[1]), "=r"(r[2]), "=r"(r[3]) : "r"(addr));
}

__device__ __forceinline__ void ldmatrix_x4_trans(unsigned* r, unsigned addr)
{
    asm volatile("ldmatrix.sync.aligned.m8n8.x4.trans.shared.b16 {%0,%1,%2,%3}, [%4];"
        : "=r"(r[0]), "=r"(r[1]), "=r"(r[2]), "=r"(r[3]) : "r"(addr));
}

__device__ __forceinline__ void cpasync16(void* dst_sh, const void* src)
{
    unsigned sh = (unsigned)__cvta_generic_to_shared(dst_sh);
    asm volatile("cp.async.cg.shared.global [%0], [%1], 16;\n" :: "r"(sh), "l"(src));
}

// ---------------------------------------------------------------------------
// bf16-split GEMM (unchanged)
// ---------------------------------------------------------------------------
#define GS_STRIDE 40
#define GS_TILE   (128 * GS_STRIDE)
#define GS_STAGE  (4 * GS_TILE)
#define GEMM_SMEM_BYTES (2 * GS_STAGE * 2)   // 81920

__global__ __launch_bounds__(256)
void gemm_split_kernel(const __nv_bfloat16* __restrict__ Ah, const __nv_bfloat16* __restrict__ Al,
                       long long aStrideZ,
                       const __nv_bfloat16* __restrict__ Bh, const __nv_bfloat16* __restrict__ Bl,
                       long long bStrideZ,
                       float* C, __nv_bfloat16* Chi, __nv_bfloat16* Clo, long long cStrideZ,
                       const float* b0, const float* b1, const float* b2,
                       int M)
{
    extern __shared__ __nv_bfloat16 smem[];
    int z = blockIdx.z;
    Ah += (long long)z * aStrideZ;
    Al += (long long)z * aStrideZ;
    Bh += (long long)z * bStrideZ;
    Bl += (long long)z * bStrideZ;
    const float* bias = (z == 0) ? b0 : (z == 1) ? b1 : b2;

    int tid  = threadIdx.x;
    int lane = tid & 31;
    int warp = tid >> 5;
    int wm = (warp & 1) * 64;
    int wn = (warp >> 1) * 32;
    int row0 = blockIdx.y * 128;
    int col0 = blockIdx.x * 128;

    int cp_arr[8], cp_row[8], cp_c[8];
#pragma unroll
    for (int i = 0; i < 8; i++) {
        cp_arr[i] = i >> 1;
        int idx2 = ((i & 1) << 8) + tid;
        cp_row[i] = idx2 >> 2;
        cp_c[i] = (idx2 & 3) * 8;
    }

    float acc[4][4][4];
#pragma unroll
    for (int im = 0; im < 4; im++)
#pragma unroll
        for (int in_ = 0; in_ < 4; in_++)
#pragma unroll
            for (int r = 0; r < 4; r++) acc[im][in_][r] = 0.f;

    const int nIt = Dc / 32;

    auto load_stage = [&](int it, int s) {
        __nv_bfloat16* st = smem + s * GS_STAGE;
        int k0 = it * 32;
#pragma unroll
        for (int i = 0; i < 8; i++) {
            const __nv_bfloat16* src;
            int row = cp_row[i];
            int c = cp_c[i];
            if (cp_arr[i] == 0)      src = Ah + (long long)(row0 + row) * Dc + k0 + c;
            else if (cp_arr[i] == 1) src = Al + (long long)(row0 + row) * Dc + k0 + c;
            else if (cp_arr[i] == 2) src = Bh + (long long)(col0 + row) * Dc + k0 + c;
            else                     src = Bl + (long long)(col0 + row) * Dc + k0 + c;
            cpasync16(st + cp_arr[i] * GS_TILE + row * GS_STRIDE + c, src);
        }
        asm volatile("cp.async.commit_group;\n" ::);
    };

    load_stage(0, 0);

    for (int it = 0; it < nIt; it++) {
        int buf = it & 1;
        if (it + 1 < nIt) {
            load_stage(it + 1, buf ^ 1);
            asm volatile("cp.async.wait_group 1;\n" ::);
        } else {
            asm volatile("cp.async.wait_group 0;\n" ::);
        }
        __syncthreads();

        const __nv_bfloat16* sAh = smem + buf * GS_STAGE;
        const __nv_bfloat16* sAl = sAh + GS_TILE;
        const __nv_bfloat16* sBh = sAl + GS_TILE;
        const __nv_bfloat16* sBl = sBh + GS_TILE;

#pragma unroll
        for (int kk = 0; kk < 32; kk += 16) {
            int acol = kk + 2 * (lane & 3);
            unsigned a_h[4][4], a_l[4][4];
#pragma unroll
            for (int im = 0; im < 4; im++) {
                int rbase = wm + im * 16 + (lane >> 2);
#pragma unroll
                for (int r = 0; r < 4; r++) {
                    int row = rbase + (r & 1) * 8;
                    int col = acol + (r >> 1) * 8;
                    a_h[im][r] = *(const unsigned*)&sAh[row * GS_STRIDE + col];
                    a_l[im][r] = *(const unsigned*)&sAl[row * GS_STRIDE + col];
                }
            }
            unsigned b_h[4][2], b_l[4][2];
#pragma unroll
            for (int in_ = 0; in_ < 4; in_++) {
                int nrow = wn + in_ * 8 + (lane >> 2);
#pragma unroll
                for (int r = 0; r < 2; r++) {
                    int col = acol + r * 8;
                    b_h[in_][r] = *(const unsigned*)&sBh[nrow * GS_STRIDE + col];
                    b_l[in_][r] = *(const unsigned*)&sBl[nrow * GS_STRIDE + col];
                }
            }
#pragma unroll
            for (int im = 0; im < 4; im++)
#pragma unroll
                for (int in_ = 0; in_ < 4; in_++) {
                    mma_bf16(acc[im][in_], a_h[im], b_h[in_]);
                    mma_bf16(acc[im][in_], a_h[im], b_l[in_]);
                    mma_bf16(acc[im][in_], a_l[im], b_h[in_]);
                }
        }
        __syncthreads();
    }

#pragma unroll
    for (int im = 0; im < 4; im++) {
#pragma unroll
        for (int in_ = 0; in_ < 4; in_++) {
            int row = row0 + wm + im * 16 + (lane >> 2);
            int col = col0 + wn + in_ * 8 + 2 * (lane & 3);
            float2 bv = *(const float2*)&bias[col];
            float o0 = acc[im][in_][0] + bv.x, o1 = acc[im][in_][1] + bv.y;
            float o2 = acc[im][in_][2] + bv.x, o3 = acc[im][in_][3] + bv.y;
            long long cb = (long long)z * cStrideZ;
            if (C) {
                *(float2*)&C[cb + (long long)row * Dc + col]       = make_float2(o0, o1);
                *(float2*)&C[cb + (long long)(row + 8) * Dc + col] = make_float2(o2, o3);
            } else {
                __nv_bfloat16 h0, l0, h1, l1, h2, l2, h3, l3;
                split_bf16(o0, h0, l0); split_bf16(o1, h1, l1);
                split_bf16(o2, h2, l2); split_bf16(o3, h3, l3);
                *(__nv_bfloat162*)&Chi[cb + (long long)row * Dc + col]       = __nv_bfloat162(h0, h1);
                *(__nv_bfloat162*)&Clo[cb + (long long)row * Dc + col]       = __nv_bfloat162(l0, l1);
                *(__nv_bfloat162*)&Chi[cb + (long long)(row + 8) * Dc + col] = __nv_bfloat162(h2, h3);
                *(__nv_bfloat162*)&Clo[cb + (long long)(row + 8) * Dc + col] = __nv_bfloat162(l2, l3);
            }
        }
    }
}

// ---------------------------------------------------------------------------
// Tensor-core banded attention (round-7 flow + ldmatrix fragment loads).
// Layout (bytes):
//   [0, 9216)         sQh (64 x 72 bf16)
//   [9216, 18432)     sQl
//   [18432, 36864)    sKh (128 x 72)
//   [36864, 55296)    sKl
//   [55296, 89088)    sS  (64 x 132 fp32)
//   [89088, 106496)   sPh (64 x 136 bf16)
//   [106496, 123904)  sPl
//   [123904, 142336)  sVh (128 x 72, row-major)
//   [142336, 160768)  sVl
//   [160768, 161024)  sinv (64 fp32)
// ---------------------------------------------------------------------------
#define AT_STRIDE 72
#define AS_STRIDE 132
#define AP_STRIDE 136
#define O_QH 0
#define O_QL 9216
#define O_KH 18432
#define O_KL 36864
#define O_SS 55296
#define O_PH 89088
#define O_PL 106496
#define O_VH 123904
#define O_VL 142336
#define O_SINV 160768
#define ATTN_SMEM_BYTES 161024

__global__ __launch_bounds__(256)
void attn_mma_kernel(const __nv_bfloat16* __restrict__ QKVhi,
                     const __nv_bfloat16* __restrict__ QKVlo,
                     __nv_bfloat16* __restrict__ Chi, __nv_bfloat16* __restrict__ Clo,
                     float* __restrict__ A1, float* __restrict__ A2)
{
    extern __shared__ char smraw[];
    __nv_bfloat16* sQh = (__nv_bfloat16*)(smraw + O_QH);
    __nv_bfloat16* sQl = (__nv_bfloat16*)(smraw + O_QL);
    __nv_bfloat16* sKh = (__nv_bfloat16*)(smraw + O_KH);
    __nv_bfloat16* sKl = (__nv_bfloat16*)(smraw + O_KL);
    float*         sS  = (float*)(smraw + O_SS);
    __nv_bfloat16* sPh = (__nv_bfloat16*)(smraw + O_PH);
    __nv_bfloat16* sPl = (__nv_bfloat16*)(smraw + O_PL);
    __nv_bfloat16* sVh = (__nv_bfloat16*)(smraw + O_VH);
    __nv_bfloat16* sVl = (__nv_bfloat16*)(smraw + O_VL);
    float*         sinv = (float*)(smraw + O_SINV);
    unsigned smem_u32 = (unsigned)__cvta_generic_to_shared(smraw);

    int tid  = threadIdx.x;
    int lane = tid & 31;
    int warp = tid >> 5;
    int q0 = blockIdx.x * 64;
    int h  = blockIdx.y;
    int zz = blockIdx.z;
    int b  = zz >> 1;
    int which = zz & 1;
    int k0 = q0 - HALFW;
    const float scale = 0.125f;

    const long long plane = (long long)M_PROJ * Dc;
    const __nv_bfloat16 *Qh, *Ql, *Kh, *Kl, *Vh, *Vl;
    int rowOffset;
    float* Aout;
    if (which == 0) {
        Qh = QKVhi;           Ql = QKVlo;
        Kh = QKVhi + plane;   Kl = QKVlo + plane;
        Vh = QKVhi + 2*plane; Vl = QKVlo + 2*plane;
        rowOffset = 0;  Aout = A1;
    } else {
        Qh = QKVhi + plane;   Ql = QKVlo + plane;
        Kh = QKVhi;           Kl = QKVlo;
        Vh = QKVhi;           Vl = QKVlo;
        rowOffset = Pc; Aout = A2;
    }
    long long headBase = (long long)b * Pc * Dc + (long long)h * DKc;
    const uint4 zero4 = make_uint4(0, 0, 0, 0);

    // Q tile (64 x 64)
    for (int t = tid; t < 512; t += 256) {
        int r = t >> 3, c = (t & 7) * 8;
        long long src = headBase + (long long)(q0 + r) * Dc + c;
        *(uint4*)&sQh[r * AT_STRIDE + c] = *(const uint4*)&Qh[src];
        *(uint4*)&sQl[r * AT_STRIDE + c] = *(const uint4*)&Ql[src];
    }
    // K + V tiles (128 x 64), row-major, zero-padded edges
    for (int t = tid; t < 1024; t += 256) {
        int r = t >> 3, c = (t & 7) * 8;
        int j = k0 + r;
        uint4 kh = zero4, kl = zero4, vh = zero4, vl = zero4;
        if (j >= 0 && j < Pc) {
            long long src = headBase + (long long)j * Dc + c;
            kh = *(const uint4*)&Kh[src];
            kl = *(const uint4*)&Kl[src];
            vh = *(const uint4*)&Vh[src];
            vl = *(const uint4*)&Vl[src];
        }
        *(uint4*)&sKh[r * AT_STRIDE + c] = kh;
        *(uint4*)&sKl[r * AT_STRIDE + c] = kl;
        *(uint4*)&sVh[r * AT_STRIDE + c] = vh;
        *(uint4*)&sVl[r * AT_STRIDE + c] = vl;
    }
    __syncthreads();

    int m0 = (warp & 1) * 32;

    // ---- S = Q*K^T (m32 x n32 per warp, k64), ldmatrix fragments ----
    {
        int n0w = (warp >> 1) * 32;
        float sacc[2][4][4];
#pragma unroll
        for (int mi = 0; mi < 2; mi++)
#pragma unroll
            for (int ni = 0; ni < 4; ni++)
#pragma unroll
                for (int r = 0; r < 4; r++) sacc[mi][ni][r] = 0.f;

#pragma unroll
        for (int ks = 0; ks < 4; ks++) {
            int kc = ks * 16;
            unsigned ah[2][4], al[2][4];
#pragma unroll
            for (int mi = 0; mi < 2; mi++) {
                int row = m0 + mi * 16 + (lane & 15);
                int col = kc + 8 * (lane >> 4);
                unsigned off = (unsigned)(row * AT_STRIDE + col) * 2;
                ldmatrix_x4(ah[mi], smem_u32 + O_QH + off);
                ldmatrix_x4(al[mi], smem_u32 + O_QL + off);
            }
            unsigned bh[4][2], bl[4][2];
#pragma unroll
            for (int nt = 0; nt < 2; nt++) {
                int row = n0w + nt * 16 + (lane & 7) + 8 * (lane >> 4);
                int col = kc + 8 * ((lane >> 3) & 1);
                unsigned off = (unsigned)(row * AT_STRIDE + col) * 2;
                unsigned th[4], tl[4];
                ldmatrix_x4(th, smem_u32 + O_KH + off);
                ldmatrix_x4(tl, smem_u32 + O_KL + off);
                bh[2*nt][0] = th[0]; bh[2*nt][1] = th[1];
                bh[2*nt+1][0] = th[2]; bh[2*nt+1][1] = th[3];
                bl[2*nt][0] = tl[0]; bl[2*nt][1] = tl[1];
                bl[2*nt+1][0] = tl[2]; bl[2*nt+1][1] = tl[3];
            }
#pragma unroll
            for (int mi = 0; mi < 2; mi++)
#pragma unroll
                for (int ni = 0; ni < 4; ni++) {
                    mma_bf16(sacc[mi][ni], ah[mi], bh[ni]);
                    mma_bf16(sacc[mi][ni], ah[mi], bl[ni]);
                    mma_bf16(sacc[mi][ni], al[mi], bh[ni]);
                }
        }
        // write S to smem fp32
#pragma unroll
        for (int mi = 0; mi < 2; mi++)
#pragma unroll
            for (int ni = 0; ni < 4; ni++) {
                int r = m0 + mi * 16 + (lane >> 2);
                int cc = n0w + ni * 8 + 2 * (lane & 3);
                *(float2*)&sS[r * AS_STRIDE + cc] =
                    make_float2(sacc[mi][ni][0], sacc[mi][ni][1]);
                *(float2*)&sS[(r + 8) * AS_STRIDE + cc] =
                    make_float2(sacc[mi][ni][2], sacc[mi][ni][3]);
            }
    }
    __syncthreads();

    // ---- softmax (fp32): unnormalized p -> sS, bf16 hi/lo -> sPh/sPl ----
    {
        int qi = tid >> 2;
        int p  = tid & 3;
        int i_glob = q0 + qi;
        int jlo = i_glob - HALFW; if (jlo < 0) jlo = 0;
        int jhi = i_glob + HALFW; if (jhi > Pc - 1) jhi = Pc - 1;
        int kjlo = jlo - k0;
        int kjhi = jhi - k0;
        float* srow = &sS[qi * AS_STRIDE];
        float m = -1e30f;
#pragma unroll 8
        for (int t = 0; t < 32; t++) {
            int kj = p + 4 * t;
            if (kj >= kjlo && kj <= kjhi) m = fmaxf(m, srow[kj]);
        }
        m = fmaxf(m, __shfl_xor_sync(0xffffffffu, m, 1));
        m = fmaxf(m, __shfl_xor_sync(0xffffffffu, m, 2));
        float sum = 0.f;
#pragma unroll 8
        for (int t = 0; t < 32; t++) {
            int kj = p + 4 * t;
            float pv = 0.f;
            if (kj >= kjlo && kj <= kjhi) {
                pv = __expf(scale * (srow[kj] - m));
                sum += pv;
            }
            srow[kj] = pv;
            __nv_bfloat16 hh, ll;
            split_bf16(pv, hh, ll);
            sPh[qi * AP_STRIDE + kj] = hh;
            sPl[qi * AP_STRIDE + kj] = ll;
        }
        sum += __shfl_xor_sync(0xffffffffu, sum, 1);
        sum += __shfl_xor_sync(0xffffffffu, sum, 2);
        if (p == 0) sinv[qi] = 1.0f / sum;
    }
    __syncthreads();

    // ---- fused dense A write (coalesced rows, streaming stores, fp32 src) ----
    if (Aout) {
        int j0 = tid * 4;
        long long abase = ((long long)b * Hc + h) * Pc * (long long)Pc;
#pragma unroll 2
        for (int r = 0; r < 64; r++) {
            int i_glob = q0 + r;
            int jlo = i_glob - HALFW; if (jlo < 0) jlo = 0;
            int jhi = i_glob + HALFW; if (jhi > Pc - 1) jhi = Pc - 1;
            float inv = sinv[r];
            const float* srow = &sS[r * AS_STRIDE];
            float4 v = make_float4(0.f, 0.f, 0.f, 0.f);
            if (j0 + 3 >= jlo && j0 <= jhi) {
                int j;
                j = j0 + 0; if (j >= jlo && j <= jhi) v.x = srow[j - k0] * inv;
                j = j0 + 1; if (j >= jlo && j <= jhi) v.y = srow[j - k0] * inv;
                j = j0 + 2; if (j >= jlo && j <= jhi) v.z = srow[j - k0] * inv;
                j = j0 + 3; if (j >= jlo && j <= jhi) v.w = srow[j - k0] * inv;
            }
            __stcs((float4*)&Aout[abase + (long long)i_glob * Pc + j0], v);
        }
    }

    // ---- O = P*V (m32 x n16 per warp, k128), ldmatrix P + ldmatrix-trans V ----
    {
        int n0o = (warp >> 1) * 16;
        float oacc[2][2][4];
#pragma unroll
        for (int mi = 0; mi < 2; mi++)
#pragma unroll
            for (int ni = 0; ni < 2; ni++)
#pragma unroll
                for (int r = 0; r < 4; r++) oacc[mi][ni][r] = 0.f;

#pragma unroll
        for (int ks = 0; ks < 8; ks++) {
            int kc = ks * 16;
            unsigned ah[2][4], al[2][4];
#pragma unroll
            for (int mi = 0; mi < 2; mi++) {
                int row = m0 + mi * 16 + (lane & 15);
                int col = kc + 8 * (lane >> 4);
                unsigned off = (unsigned)(row * AP_STRIDE + col) * 2;
                ldmatrix_x4(ah[mi], smem_u32 + O_PH + off);
                ldmatrix_x4(al[mi], smem_u32 + O_PL + off);
            }
            unsigned bh[2][2], bl[2][2];
            {
                int row = kc + (lane & 15);
                int col = n0o + 8 * (lane >> 4);
                unsigned off = (unsigned)(row * AT_STRIDE + col) * 2;
                unsigned th[4], tl[4];
                ldmatrix_x4_trans(th, smem_u32 + O_VH + off);
                ldmatrix_x4_trans(tl, smem_u32 + O_VL + off);
                bh[0][0] = th[0]; bh[0][1] = th[1];
                bh[1][0] = th[2]; bh[1][1] = th[3];
                bl[0][0] = tl[0]; bl[0][1] = tl[1];
                bl[1][0] = tl[2]; bl[1][1] = tl[3];
            }
#pragma unroll
            for (int mi = 0; mi < 2; mi++)
#pragma unroll
                for (int ni = 0; ni < 2; ni++) {
                    mma_bf16(oacc[mi][ni], ah[mi], bh[ni]);
                    mma_bf16(oacc[mi][ni], ah[mi], bl[ni]);
                    mma_bf16(oacc[mi][ni], al[mi], bh[ni]);
                }
        }

#pragma unroll
        for (int mi = 0; mi < 2; mi++)
#pragma unroll
            for (int ni = 0; ni < 2; ni++) {
                int qi0 = m0 + mi * 16 + (lane >> 2);
                int d   = n0o + ni * 8 + 2 * (lane & 3);
                float inv0 = sinv[qi0];
                float inv1 = sinv[qi0 + 8];
                float o0 = oacc[mi][ni][0] * inv0, o1 = oacc[mi][ni][1] * inv0;
                float o2 = oacc[mi][ni][2] * inv1, o3 = oacc[mi][ni][3] * inv1;
                long long dst0 = ((long long)b * CONCAT_P + rowOffset + q0 + qi0) * Dc
                                 + h * DKc + d;
                long long dst1 = dst0 + 8LL * Dc;
                __nv_bfloat16 h0, l0, h1, l1, h2, l2, h3, l3;
                split_bf16(o0, h0, l0); split_bf16(o1, h1, l1);
                split_bf16(o2, h2, l2); split_bf16(o3, h3, l3);
                *(__nv_bfloat162*)&Chi[dst0] = __nv_bfloat162(h0, h1);
                *(__nv_bfloat162*)&Clo[dst0] = __nv_bfloat162(l0, l1);
                *(__nv_bfloat162*)&Chi[dst1] = __nv_bfloat162(h2, h3);
                *(__nv_bfloat162*)&Clo[dst1] = __nv_bfloat162(l2, l3);
            }
    }
}

// ---------------------------------------------------------------------------
extern "C" void kernel_launch(void* const* d_in, const int* in_sizes, int n_in,
                              void* d_out, int out_size)
{
    const float* queries = (const float*)d_in[0];
    const float* keys    = (const float*)d_in[1];
    const float* values  = (const float*)d_in[2];
    const float* Wq = (const float*)d_in[3];
    const float* bq = (const float*)d_in[4];
    const float* Wk = (const float*)d_in[5];
    const float* bk = (const float*)d_in[6];
    const float* Wv = (const float*)d_in[7];
    const float* bv = (const float*)d_in[8];
    const float* Wo = (const float*)d_in[9];
    const float* bo = (const float*)d_in[10];

    float* out = (float*)d_out;

    __nv_bfloat16 *Ahi, *Alo, *Bhi, *Blo, *QKVhi, *QKVlo, *Chi, *Clo;
    cudaGetSymbolAddress((void**)&Ahi, g_Ahi);
    cudaGetSymbolAddress((void**)&Alo, g_Alo);
    cudaGetSymbolAddress((void**)&Bhi, g_Bhi);
    cudaGetSymbolAddress((void**)&Blo, g_Blo);
    cudaGetSymbolAddress((void**)&QKVhi, g_QKVhi);
    cudaGetSymbolAddress((void**)&QKVlo, g_QKVlo);
    cudaGetSymbolAddress((void**)&Chi, g_Chi);
    cudaGetSymbolAddress((void**)&Clo, g_Clo);

    static int attr_set = 0;
    if (!attr_set) {
        cudaFuncSetAttribute(attn_mma_kernel,
                             cudaFuncAttributeMaxDynamicSharedMemorySize, ATTN_SMEM_BYTES);
        cudaFuncSetAttribute(gemm_split_kernel,
                             cudaFuncAttributeMaxDynamicSharedMemorySize, GEMM_SMEM_BYTES);
        attr_set = 1;
    }

    const long long mainN = (long long)M_OUT * Dc;
    const long long aN    = (long long)Bc * Hc * Pc * Pc;
    float* A1 = nullptr;
    float* A2 = nullptr;
    if ((long long)out_size >= mainN + 2 * aN) {
        A1 = out + mainN;
        A2 = A1 + aN;
    }

    split_a_kernel<<<dim3(256, 1, 3), 256>>>(queries, keys, values, Ahi, Alo);
    split_b_kernel<<<dim3(16, 16, 4), dim3(32, 8)>>>(Wq, Wk, Wv, Wo, Bhi, Blo);

    const long long aStride = (long long)M_PROJ * Dc;
    const long long bStride = (long long)Dc * Dc;

    gemm_split_kernel<<<dim3(Dc / 128, M_PROJ / 128, 3), 256, GEMM_SMEM_BYTES>>>(
        Ahi, Alo, aStride, Bhi, Blo, bStride,
        nullptr, QKVhi, QKVlo, aStride, bq, bk, bv, M_PROJ);

    dim3 ga(Pc / 64, Hc, Bc * 2);
    attn_mma_kernel<<<ga, 256, ATTN_SMEM_BYTES>>>(QKVhi, QKVlo, Chi, Clo, A1, A2);

    gemm_split_kernel<<<dim3(Dc / 128, M_OUT / 128, 1), 256, GEMM_SMEM_BYTES>>>(
        Chi, Clo, 0, Bhi + 3 * bStride, Blo + 3 * bStride, 0,
        out, nullptr, nullptr, 0, bo, bo, bo, M_OUT);
}

// round 10
// speedup vs baseline: 1.1419x; 1.0159x over previous
#include <cuda_runtime.h>
#include <cuda_bf16.h>
#include <math.h>

#define Bc   4
#define Pc   1024
#define Dc   512
#define Hc   8
#define DKc  64
#define HALFW 32
#define CONCAT_P (2*Pc)

#define M_PROJ (Bc * Pc)        // 4096
#define M_OUT  (Bc * CONCAT_P)  // 8192

__device__ __nv_bfloat16 g_Ahi[3 * M_PROJ * Dc];
__device__ __nv_bfloat16 g_Alo[3 * M_PROJ * Dc];
__device__ __nv_bfloat16 g_Bhi[4 * Dc * Dc];        // weights [n][k]
__device__ __nv_bfloat16 g_Blo[4 * Dc * Dc];
__device__ __nv_bfloat16 g_QKVhi[3 * M_PROJ * Dc];
__device__ __nv_bfloat16 g_QKVlo[3 * M_PROJ * Dc];
__device__ __nv_bfloat16 g_Chi[M_OUT * Dc];
__device__ __nv_bfloat16 g_Clo[M_OUT * Dc];

// ---------------------------------------------------------------------------
__device__ __forceinline__ void split_bf16(float v, __nv_bfloat16& hi, __nv_bfloat16& lo)
{
    hi = __float2bfloat16(v);
    lo = __float2bfloat16(v - __bfloat162float(hi));
}

__global__ void split_a_kernel(const float* __restrict__ s0, const float* __restrict__ s1,
                               const float* __restrict__ s2,
                               __nv_bfloat16* __restrict__ hi, __nv_bfloat16* __restrict__ lo)
{
    int z = blockIdx.z;
    const float* src = (z == 0) ? s0 : (z == 1) ? s1 : s2;
    long long base = (long long)z * M_PROJ * Dc;
    long long n4 = (long long)M_PROJ * Dc / 4;
    long long idx = (long long)blockIdx.x * blockDim.x + threadIdx.x;
    long long stride = (long long)gridDim.x * blockDim.x;
    for (long long i = idx; i < n4; i += stride) {
        float4 v = ((const float4*)src)[i];
        __nv_bfloat16 h[4], l[4];
        split_bf16(v.x, h[0], l[0]);
        split_bf16(v.y, h[1], l[1]);
        split_bf16(v.z, h[2], l[2]);
        split_bf16(v.w, h[3], l[3]);
        long long o = base + i * 4;
        *(__nv_bfloat162*)&hi[o]     = __nv_bfloat162(h[0], h[1]);
        *(__nv_bfloat162*)&hi[o + 2] = __nv_bfloat162(h[2], h[3]);
        *(__nv_bfloat162*)&lo[o]     = __nv_bfloat162(l[0], l[1]);
        *(__nv_bfloat162*)&lo[o + 2] = __nv_bfloat162(l[2], l[3]);
    }
}

__global__ void split_b_kernel(const float* __restrict__ w0, const float* __restrict__ w1,
                               const float* __restrict__ w2, const float* __restrict__ w3,
                               __nv_bfloat16* __restrict__ hi, __nv_bfloat16* __restrict__ lo)
{
    __shared__ float t[32][33];
    int z = blockIdx.z;
    const float* W = (z == 0) ? w0 : (z == 1) ? w1 : (z == 2) ? w2 : w3;
    long long base = (long long)z * Dc * Dc;
    int n0 = blockIdx.x * 32;
    int k0 = blockIdx.y * 32;
    int tx = threadIdx.x, ty = threadIdx.y;
#pragma unroll
    for (int i = 0; i < 4; i++)
        t[ty + i * 8][tx] = W[(long long)(k0 + ty + i * 8) * Dc + n0 + tx];
    __syncthreads();
#pragma unroll
    for (int i = 0; i < 4; i++) {
        float v = t[tx][ty + i * 8];
        long long o = base + (long long)(n0 + ty + i * 8) * Dc + k0 + tx;
        __nv_bfloat16 h, l;
        split_bf16(v, h, l);
        hi[o] = h;
        lo[o] = l;
    }
}

// ---------------------------------------------------------------------------
// mma / ldmatrix helpers
// ---------------------------------------------------------------------------
__device__ __forceinline__ void mma_bf16(float* d, const unsigned* a, const unsigned* b)
{
    asm volatile(
        "mma.sync.aligned.m16n8k16.row.col.f32.bf16.bf16.f32 "
        "{%0,%1,%2,%3}, {%4,%5,%6,%7}, {%8,%9}, {%0,%1,%2,%3};"
        : "+f"(d[0]), "+f"(d[1]), "+f"(d[2]), "+f"(d[3])
        : "r"(a[0]), "r"(a[1]), "r"(a[2]), "r"(a[3]), "r"(b[0]), "r"(b[1]));
}

__device__ __forceinline__ void ldmatrix_x4(unsigned* r, unsigned addr)
{
    asm volatile("ldmatrix.sync.aligned.m8n8.x4.shared.b16 {%0,%1,%2,%3}, [%4];"
        : "=r"(r[0]), "=r"(r[1]), "=r"(r[2]), "=r"(r[3]) : "r"(addr));
}

__device__ __forceinline__ void ldmatrix_x4_trans(unsigned* r, unsigned addr)
{
    asm volatile("ldmatrix.sync.aligned.m8n8.x4.trans.shared.b16 {%0,%1,%2,%3}, [%4];"
        : "=r"(r[0]), "=r"(r[1]), "=r"(r[2]), "=r"(r[3]) : "r"(addr));
}

__device__ __forceinline__ void cpasync16(void* dst_sh, const void* src)
{
    unsigned sh = (unsigned)__cvta_generic_to_shared(dst_sh);
    asm volatile("cp.async.cg.shared.global [%0], [%1], 16;\n" :: "r"(sh), "l"(src));
}

// ---------------------------------------------------------------------------
// bf16-split GEMM with ldmatrix fragment loads.
// C[M,512] = A[M,512] @ B^T + bias; B stored [n][k].
// Block 128x128, BK=32, 256 threads (8 warps 2m x 4n, warp 64x32), 2-stage cp.async.
// ---------------------------------------------------------------------------
#define GS_STRIDE 40
#define GS_TILE   (128 * GS_STRIDE)
#define GS_STAGE  (4 * GS_TILE)
#define GEMM_SMEM_BYTES (2 * GS_STAGE * 2)   // 81920

__global__ __launch_bounds__(256)
void gemm_split_kernel(const __nv_bfloat16* __restrict__ Ah, const __nv_bfloat16* __restrict__ Al,
                       long long aStrideZ,
                       const __nv_bfloat16* __restrict__ Bh, const __nv_bfloat16* __restrict__ Bl,
                       long long bStrideZ,
                       float* C, __nv_bfloat16* Chi, __nv_bfloat16* Clo, long long cStrideZ,
                       const float* b0, const float* b1, const float* b2,
                       int M)
{
    extern __shared__ __nv_bfloat16 smem[];
    unsigned smem_u32 = (unsigned)__cvta_generic_to_shared(smem);
    int z = blockIdx.z;
    Ah += (long long)z * aStrideZ;
    Al += (long long)z * aStrideZ;
    Bh += (long long)z * bStrideZ;
    Bl += (long long)z * bStrideZ;
    const float* bias = (z == 0) ? b0 : (z == 1) ? b1 : b2;

    int tid  = threadIdx.x;
    int lane = tid & 31;
    int warp = tid >> 5;
    int wm = (warp & 1) * 64;
    int wn = (warp >> 1) * 32;
    int row0 = blockIdx.y * 128;
    int col0 = blockIdx.x * 128;

    int cp_arr[8], cp_row[8], cp_c[8];
#pragma unroll
    for (int i = 0; i < 8; i++) {
        cp_arr[i] = i >> 1;
        int idx2 = ((i & 1) << 8) + tid;
        cp_row[i] = idx2 >> 2;
        cp_c[i] = (idx2 & 3) * 8;
    }

    float acc[4][4][4];
#pragma unroll
    for (int im = 0; im < 4; im++)
#pragma unroll
        for (int in_ = 0; in_ < 4; in_++)
#pragma unroll
            for (int r = 0; r < 4; r++) acc[im][in_][r] = 0.f;

    const int nIt = Dc / 32;

    auto load_stage = [&](int it, int s) {
        __nv_bfloat16* st = smem + s * GS_STAGE;
        int k0 = it * 32;
#pragma unroll
        for (int i = 0; i < 8; i++) {
            const __nv_bfloat16* src;
            int row = cp_row[i];
            int c = cp_c[i];
            if (cp_arr[i] == 0)      src = Ah + (long long)(row0 + row) * Dc + k0 + c;
            else if (cp_arr[i] == 1) src = Al + (long long)(row0 + row) * Dc + k0 + c;
            else if (cp_arr[i] == 2) src = Bh + (long long)(col0 + row) * Dc + k0 + c;
            else                     src = Bl + (long long)(col0 + row) * Dc + k0 + c;
            cpasync16(st + cp_arr[i] * GS_TILE + row * GS_STRIDE + c, src);
        }
        asm volatile("cp.async.commit_group;\n" ::);
    };

    load_stage(0, 0);

    for (int it = 0; it < nIt; it++) {
        int buf = it & 1;
        if (it + 1 < nIt) {
            load_stage(it + 1, buf ^ 1);
            asm volatile("cp.async.wait_group 1;\n" ::);
        } else {
            asm volatile("cp.async.wait_group 0;\n" ::);
        }
        __syncthreads();

        unsigned stage_base = smem_u32 + (unsigned)(buf * GS_STAGE * 2);
        unsigned uAh = stage_base;
        unsigned uAl = stage_base + GS_TILE * 2;
        unsigned uBh = stage_base + 2 * GS_TILE * 2;
        unsigned uBl = stage_base + 3 * GS_TILE * 2;

#pragma unroll
        for (int kk = 0; kk < 32; kk += 16) {
            // A fragments: m16k16 tiles via ldmatrix (Q-mapping from attention)
            unsigned a_h[4][4], a_l[4][4];
#pragma unroll
            for (int im = 0; im < 4; im++) {
                int row = wm + im * 16 + (lane & 15);
                int col = kk + 8 * (lane >> 4);
                unsigned off = (unsigned)(row * GS_STRIDE + col) * 2;
                ldmatrix_x4(a_h[im], uAh + off);
                ldmatrix_x4(a_l[im], uAl + off);
            }
            // B fragments: [n][k] rows via ldmatrix (K-mapping from attention)
            unsigned b_h[4][2], b_l[4][2];
#pragma unroll
            for (int nt = 0; nt < 2; nt++) {
                int row = wn + nt * 16 + (lane & 7) + 8 * (lane >> 4);
                int col = kk + 8 * ((lane >> 3) & 1);
                unsigned off = (unsigned)(row * GS_STRIDE + col) * 2;
                unsigned th[4], tl[4];
                ldmatrix_x4(th, uBh + off);
                ldmatrix_x4(tl, uBl + off);
                b_h[2*nt][0] = th[0];   b_h[2*nt][1] = th[1];
                b_h[2*nt+1][0] = th[2]; b_h[2*nt+1][1] = th[3];
                b_l[2*nt][0] = tl[0];   b_l[2*nt][1] = tl[1];
                b_l[2*nt+1][0] = tl[2]; b_l[2*nt+1][1] = tl[3];
            }
#pragma unroll
            for (int im = 0; im < 4; im++)
#pragma unroll
                for (int in_ = 0; in_ < 4; in_++) {
                    mma_bf16(acc[im][in_], a_h[im], b_h[in_]);
                    mma_bf16(acc[im][in_], a_h[im], b_l[in_]);
                    mma_bf16(acc[im][in_], a_l[im], b_h[in_]);
                }
        }
        __syncthreads();
    }

#pragma unroll
    for (int im = 0; im < 4; im++) {
#pragma unroll
        for (int in_ = 0; in_ < 4; in_++) {
            int row = row0 + wm + im * 16 + (lane >> 2);
            int col = col0 + wn + in_ * 8 + 2 * (lane & 3);
            float2 bv = *(const float2*)&bias[col];
            float o0 = acc[im][in_][0] + bv.x, o1 = acc[im][in_][1] + bv.y;
            float o2 = acc[im][in_][2] + bv.x, o3 = acc[im][in_][3] + bv.y;
            long long cb = (long long)z * cStrideZ;
            if (C) {
                *(float2*)&C[cb + (long long)row * Dc + col]       = make_float2(o0, o1);
                *(float2*)&C[cb + (long long)(row + 8) * Dc + col] = make_float2(o2, o3);
            } else {
                __nv_bfloat16 h0, l0, h1, l1, h2, l2, h3, l3;
                split_bf16(o0, h0, l0); split_bf16(o1, h1, l1);
                split_bf16(o2, h2, l2); split_bf16(o3, h3, l3);
                *(__nv_bfloat162*)&Chi[cb + (long long)row * Dc + col]       = __nv_bfloat162(h0, h1);
                *(__nv_bfloat162*)&Clo[cb + (long long)row * Dc + col]       = __nv_bfloat162(l0, l1);
                *(__nv_bfloat162*)&Chi[cb + (long long)(row + 8) * Dc + col] = __nv_bfloat162(h2, h3);
                *(__nv_bfloat162*)&Clo[cb + (long long)(row + 8) * Dc + col] = __nv_bfloat162(l2, l3);
            }
        }
    }
}

// ---------------------------------------------------------------------------
// Tensor-core banded attention (round-9 best, unchanged).
// ---------------------------------------------------------------------------
#define AT_STRIDE 72
#define AS_STRIDE 132
#define AP_STRIDE 136
#define O_QH 0
#define O_QL 9216
#define O_KH 18432
#define O_KL 36864
#define O_SS 55296
#define O_PH 89088
#define O_PL 106496
#define O_VH 123904
#define O_VL 142336
#define O_SINV 160768
#define ATTN_SMEM_BYTES 161024

__global__ __launch_bounds__(256)
void attn_mma_kernel(const __nv_bfloat16* __restrict__ QKVhi,
                     const __nv_bfloat16* __restrict__ QKVlo,
                     __nv_bfloat16* __restrict__ Chi, __nv_bfloat16* __restrict__ Clo,
                     float* __restrict__ A1, float* __restrict__ A2)
{
    extern __shared__ char smraw[];
    __nv_bfloat16* sQh = (__nv_bfloat16*)(smraw + O_QH);
    __nv_bfloat16* sQl = (__nv_bfloat16*)(smraw + O_QL);
    __nv_bfloat16* sKh = (__nv_bfloat16*)(smraw + O_KH);
    __nv_bfloat16* sKl = (__nv_bfloat16*)(smraw + O_KL);
    float*         sS  = (float*)(smraw + O_SS);
    __nv_bfloat16* sPh = (__nv_bfloat16*)(smraw + O_PH);
    __nv_bfloat16* sPl = (__nv_bfloat16*)(smraw + O_PL);
    __nv_bfloat16* sVh = (__nv_bfloat16*)(smraw + O_VH);
    __nv_bfloat16* sVl = (__nv_bfloat16*)(smraw + O_VL);
    float*         sinv = (float*)(smraw + O_SINV);
    unsigned smem_u32 = (unsigned)__cvta_generic_to_shared(smraw);

    int tid  = threadIdx.x;
    int lane = tid & 31;
    int warp = tid >> 5;
    int q0 = blockIdx.x * 64;
    int h  = blockIdx.y;
    int zz = blockIdx.z;
    int b  = zz >> 1;
    int which = zz & 1;
    int k0 = q0 - HALFW;
    const float scale = 0.125f;

    const long long plane = (long long)M_PROJ * Dc;
    const __nv_bfloat16 *Qh, *Ql, *Kh, *Kl, *Vh, *Vl;
    int rowOffset;
    float* Aout;
    if (which == 0) {
        Qh = QKVhi;           Ql = QKVlo;
        Kh = QKVhi + plane;   Kl = QKVlo + plane;
        Vh = QKVhi + 2*plane; Vl = QKVlo + 2*plane;
        rowOffset = 0;  Aout = A1;
    } else {
        Qh = QKVhi + plane;   Ql = QKVlo + plane;
        Kh = QKVhi;           Kl = QKVlo;
        Vh = QKVhi;           Vl = QKVlo;
        rowOffset = Pc; Aout = A2;
    }
    long long headBase = (long long)b * Pc * Dc + (long long)h * DKc;
    const uint4 zero4 = make_uint4(0, 0, 0, 0);

    // Q tile (64 x 64)
    for (int t = tid; t < 512; t += 256) {
        int r = t >> 3, c = (t & 7) * 8;
        long long src = headBase + (long long)(q0 + r) * Dc + c;
        *(uint4*)&sQh[r * AT_STRIDE + c] = *(const uint4*)&Qh[src];
        *(uint4*)&sQl[r * AT_STRIDE + c] = *(const uint4*)&Ql[src];
    }
    // K + V tiles (128 x 64), row-major, zero-padded edges
    for (int t = tid; t < 1024; t += 256) {
        int r = t >> 3, c = (t & 7) * 8;
        int j = k0 + r;
        uint4 kh = zero4, kl = zero4, vh = zero4, vl = zero4;
        if (j >= 0 && j < Pc) {
            long long src = headBase + (long long)j * Dc + c;
            kh = *(const uint4*)&Kh[src];
            kl = *(const uint4*)&Kl[src];
            vh = *(const uint4*)&Vh[src];
            vl = *(const uint4*)&Vl[src];
        }
        *(uint4*)&sKh[r * AT_STRIDE + c] = kh;
        *(uint4*)&sKl[r * AT_STRIDE + c] = kl;
        *(uint4*)&sVh[r * AT_STRIDE + c] = vh;
        *(uint4*)&sVl[r * AT_STRIDE + c] = vl;
    }
    __syncthreads();

    int m0 = (warp & 1) * 32;

    // ---- S = Q*K^T (m32 x n32 per warp, k64), ldmatrix fragments ----
    {
        int n0w = (warp >> 1) * 32;
        float sacc[2][4][4];
#pragma unroll
        for (int mi = 0; mi < 2; mi++)
#pragma unroll
            for (int ni = 0; ni < 4; ni++)
#pragma unroll
                for (int r = 0; r < 4; r++) sacc[mi][ni][r] = 0.f;

#pragma unroll
        for (int ks = 0; ks < 4; ks++) {
            int kc = ks * 16;
            unsigned ah[2][4], al[2][4];
#pragma unroll
            for (int mi = 0; mi < 2; mi++) {
                int row = m0 + mi * 16 + (lane & 15);
                int col = kc + 8 * (lane >> 4);
                unsigned off = (unsigned)(row * AT_STRIDE + col) * 2;
                ldmatrix_x4(ah[mi], smem_u32 + O_QH + off);
                ldmatrix_x4(al[mi], smem_u32 + O_QL + off);
            }
            unsigned bh[4][2], bl[4][2];
#pragma unroll
            for (int nt = 0; nt < 2; nt++) {
                int row = n0w + nt * 16 + (lane & 7) + 8 * (lane >> 4);
                int col = kc + 8 * ((lane >> 3) & 1);
                unsigned off = (unsigned)(row * AT_STRIDE + col) * 2;
                unsigned th[4], tl[4];
                ldmatrix_x4(th, smem_u32 + O_KH + off);
                ldmatrix_x4(tl, smem_u32 + O_KL + off);
                bh[2*nt][0] = th[0]; bh[2*nt][1] = th[1];
                bh[2*nt+1][0] = th[2]; bh[2*nt+1][1] = th[3];
                bl[2*nt][0] = tl[0]; bl[2*nt][1] = tl[1];
                bl[2*nt+1][0] = tl[2]; bl[2*nt+1][1] = tl[3];
            }
#pragma unroll
            for (int mi = 0; mi < 2; mi++)
#pragma unroll
                for (int ni = 0; ni < 4; ni++) {
                    mma_bf16(sacc[mi][ni], ah[mi], bh[ni]);
                    mma_bf16(sacc[mi][ni], ah[mi], bl[ni]);
                    mma_bf16(sacc[mi][ni], al[mi], bh[ni]);
                }
        }
        // write S to smem fp32
#pragma unroll
        for (int mi = 0; mi < 2; mi++)
#pragma unroll
            for (int ni = 0; ni < 4; ni++) {
                int r = m0 + mi * 16 + (lane >> 2);
                int cc = n0w + ni * 8 + 2 * (lane & 3);
                *(float2*)&sS[r * AS_STRIDE + cc] =
                    make_float2(sacc[mi][ni][0], sacc[mi][ni][1]);
                *(float2*)&sS[(r + 8) * AS_STRIDE + cc] =
                    make_float2(sacc[mi][ni][2], sacc[mi][ni][3]);
            }
    }
    __syncthreads();

    // ---- softmax (fp32): unnormalized p -> sS, bf16 hi/lo -> sPh/sPl ----
    {
        int qi = tid >> 2;
        int p  = tid & 3;
        int i_glob = q0 + qi;
        int jlo = i_glob - HALFW; if (jlo < 0) jlo = 0;
        int jhi = i_glob + HALFW; if (jhi > Pc - 1) jhi = Pc - 1;
        int kjlo = jlo - k0;
        int kjhi = jhi - k0;
        float* srow = &sS[qi * AS_STRIDE];
        float m = -1e30f;
#pragma unroll 8
        for (int t = 0; t < 32; t++) {
            int kj = p + 4 * t;
            if (kj >= kjlo && kj <= kjhi) m = fmaxf(m, srow[kj]);
        }
        m = fmaxf(m, __shfl_xor_sync(0xffffffffu, m, 1));
        m = fmaxf(m, __shfl_xor_sync(0xffffffffu, m, 2));
        float sum = 0.f;
#pragma unroll 8
        for (int t = 0; t < 32; t++) {
            int kj = p + 4 * t;
            float pv = 0.f;
            if (kj >= kjlo && kj <= kjhi) {
                pv = __expf(scale * (srow[kj] - m));
                sum += pv;
            }
            srow[kj] = pv;
            __nv_bfloat16 hh, ll;
            split_bf16(pv, hh, ll);
            sPh[qi * AP_STRIDE + kj] = hh;
            sPl[qi * AP_STRIDE + kj] = ll;
        }
        sum += __shfl_xor_sync(0xffffffffu, sum, 1);
        sum += __shfl_xor_sync(0xffffffffu, sum, 2);
        if (p == 0) sinv[qi] = 1.0f / sum;
    }
    __syncthreads();

    // ---- fused dense A write (coalesced rows, streaming stores, fp32 src) ----
    if (Aout) {
        int j0 = tid * 4;
        long long abase = ((long long)b * Hc + h) * Pc * (long long)Pc;
#pragma unroll 2
        for (int r = 0; r < 64; r++) {
            int i_glob = q0 + r;
            int jlo = i_glob - HALFW; if (jlo < 0) jlo = 0;
            int jhi = i_glob + HALFW; if (jhi > Pc - 1) jhi = Pc - 1;
            float inv = sinv[r];
            const float* srow = &sS[r * AS_STRIDE];
            float4 v = make_float4(0.f, 0.f, 0.f, 0.f);
            if (j0 + 3 >= jlo && j0 <= jhi) {
                int j;
                j = j0 + 0; if (j >= jlo && j <= jhi) v.x = srow[j - k0] * inv;
                j = j0 + 1; if (j >= jlo && j <= jhi) v.y = srow[j - k0] * inv;
                j = j0 + 2; if (j >= jlo && j <= jhi) v.z = srow[j - k0] * inv;
                j = j0 + 3; if (j >= jlo && j <= jhi) v.w = srow[j - k0] * inv;
            }
            __stcs((float4*)&Aout[abase + (long long)i_glob * Pc + j0], v);
        }
    }

    // ---- O = P*V (m32 x n16 per warp, k128), ldmatrix P + ldmatrix-trans V ----
    {
        int n0o = (warp >> 1) * 16;
        float oacc[2][2][4];
#pragma unroll
        for (int mi = 0; mi < 2; mi++)
#pragma unroll
            for (int ni = 0; ni < 2; ni++)
#pragma unroll
                for (int r = 0; r < 4; r++) oacc[mi][ni][r] = 0.f;

#pragma unroll
        for (int ks = 0; ks < 8; ks++) {
            int kc = ks * 16;
            unsigned ah[2][4], al[2][4];
#pragma unroll
            for (int mi = 0; mi < 2; mi++) {
                int row = m0 + mi * 16 + (lane & 15);
                int col = kc + 8 * (lane >> 4);
                unsigned off = (unsigned)(row * AP_STRIDE + col) * 2;
                ldmatrix_x4(ah[mi], smem_u32 + O_PH + off);
                ldmatrix_x4(al[mi], smem_u32 + O_PL + off);
            }
            unsigned bh[2][2], bl[2][2];
            {
                int row = kc + (lane & 15);
                int col = n0o + 8 * (lane >> 4);
                unsigned off = (unsigned)(row * AT_STRIDE + col) * 2;
                unsigned th[4], tl[4];
                ldmatrix_x4_trans(th, smem_u32 + O_VH + off);
                ldmatrix_x4_trans(tl, smem_u32 + O_VL + off);
                bh[0][0] = th[0]; bh[0][1] = th[1];
                bh[1][0] = th[2]; bh[1][1] = th[3];
                bl[0][0] = tl[0]; bl[0][1] = tl[1];
                bl[1][0] = tl[2]; bl[1][1] = tl[3];
            }
#pragma unroll
            for (int mi = 0; mi < 2; mi++)
#pragma unroll
                for (int ni = 0; ni < 2; ni++) {
                    mma_bf16(oacc[mi][ni], ah[mi], bh[ni]);
                    mma_bf16(oacc[mi][ni], ah[mi], bl[ni]);
                    mma_bf16(oacc[mi][ni], al[mi], bh[ni]);
                }
        }

#pragma unroll
        for (int mi = 0; mi < 2; mi++)
#pragma unroll
            for (int ni = 0; ni < 2; ni++) {
                int qi0 = m0 + mi * 16 + (lane >> 2);
                int d   = n0o + ni * 8 + 2 * (lane & 3);
                float inv0 = sinv[qi0];
                float inv1 = sinv[qi0 + 8];
                float o0 = oacc[mi][ni][0] * inv0, o1 = oacc[mi][ni][1] * inv0;
                float o2 = oacc[mi][ni][2] * inv1, o3 = oacc[mi][ni][3] * inv1;
                long long dst0 = ((long long)b * CONCAT_P + rowOffset + q0 + qi0) * Dc
                                 + h * DKc + d;
                long long dst1 = dst0 + 8LL * Dc;
                __nv_bfloat16 h0, l0, h1, l1, h2, l2, h3, l3;
                split_bf16(o0, h0, l0); split_bf16(o1, h1, l1);
                split_bf16(o2, h2, l2); split_bf16(o3, h3, l3);
                *(__nv_bfloat162*)&Chi[dst0] = __nv_bfloat162(h0, h1);
                *(__nv_bfloat162*)&Clo[dst0] = __nv_bfloat162(l0, l1);
                *(__nv_bfloat162*)&Chi[dst1] = __nv_bfloat162(h2, h3);
                *(__nv_bfloat162*)&Clo[dst1] = __nv_bfloat162(l2, l3);
            }
    }
}

// ---------------------------------------------------------------------------
extern "C" void kernel_launch(void* const* d_in, const int* in_sizes, int n_in,
                              void* d_out, int out_size)
{
    const float* queries = (const float*)d_in[0];
    const float* keys    = (const float*)d_in[1];
    const float* values  = (const float*)d_in[2];
    const float* Wq = (const float*)d_in[3];
    const float* bq = (const float*)d_in[4];
    const float* Wk = (const float*)d_in[5];
    const float* bk = (const float*)d_in[6];
    const float* Wv = (const float*)d_in[7];
    const float* bv = (const float*)d_in[8];
    const float* Wo = (const float*)d_in[9];
    const float* bo = (const float*)d_in[10];

    float* out = (float*)d_out;

    __nv_bfloat16 *Ahi, *Alo, *Bhi, *Blo, *QKVhi, *QKVlo, *Chi, *Clo;
    cudaGetSymbolAddress((void**)&Ahi, g_Ahi);
    cudaGetSymbolAddress((void**)&Alo, g_Alo);
    cudaGetSymbolAddress((void**)&Bhi, g_Bhi);
    cudaGetSymbolAddress((void**)&Blo, g_Blo);
    cudaGetSymbolAddress((void**)&QKVhi, g_QKVhi);
    cudaGetSymbolAddress((void**)&QKVlo, g_QKVlo);
    cudaGetSymbolAddress((void**)&Chi, g_Chi);
    cudaGetSymbolAddress((void**)&Clo, g_Clo);

    static int attr_set = 0;
    if (!attr_set) {
        cudaFuncSetAttribute(attn_mma_kernel,
                             cudaFuncAttributeMaxDynamicSharedMemorySize, ATTN_SMEM_BYTES);
        cudaFuncSetAttribute(gemm_split_kernel,
                             cudaFuncAttributeMaxDynamicSharedMemorySize, GEMM_SMEM_BYTES);
        attr_set = 1;
    }

    const long long mainN = (long long)M_OUT * Dc;
    const long long aN    = (long long)Bc * Hc * Pc * Pc;
    float* A1 = nullptr;
    float* A2 = nullptr;
    if ((long long)out_size >= mainN + 2 * aN) {
        A1 = out + mainN;
        A2 = A1 + aN;
    }

    split_a_kernel<<<dim3(256, 1, 3), 256>>>(queries, keys, values, Ahi, Alo);
    split_b_kernel<<<dim3(16, 16, 4), dim3(32, 8)>>>(Wq, Wk, Wv, Wo, Bhi, Blo);

    const long long aStride = (long long)M_PROJ * Dc;
    const long long bStride = (long long)Dc * Dc;

    gemm_split_kernel<<<dim3(Dc / 128, M_PROJ / 128, 3), 256, GEMM_SMEM_BYTES>>>(
        Ahi, Alo, aStride, Bhi, Blo, bStride,
        nullptr, QKVhi, QKVlo, aStride, bq, bk, bv, M_PROJ);

    dim3 ga(Pc / 64, Hc, Bc * 2);
    attn_mma_kernel<<<ga, 256, ATTN_SMEM_BYTES>>>(QKVhi, QKVlo, Chi, Clo, A1, A2);

    gemm_split_kernel<<<dim3(Dc / 128, M_OUT / 128, 1), 256, GEMM_SMEM_BYTES>>>(
        Chi, Clo, 0, Bhi + 3 * bStride, Blo + 3 * bStride, 0,
        out, nullptr, nullptr, 0, bo, bo, bo, M_OUT);
}

// round 11
// speedup vs baseline: 1.1983x; 1.0495x over previous
#include <cuda_runtime.h>
#include <cuda_bf16.h>
#include <math.h>

#define Bc   4
#define Pc   1024
#define Dc   512
#define Hc   8
#define DKc  64
#define HALFW 32
#define CONCAT_P (2*Pc)

#define M_PROJ (Bc * Pc)        // 4096
#define M_OUT  (Bc * CONCAT_P)  // 8192

__device__ __nv_bfloat16 g_Ahi[3 * M_PROJ * Dc];
__device__ __nv_bfloat16 g_Alo[3 * M_PROJ * Dc];
__device__ __nv_bfloat16 g_Bhi[4 * Dc * Dc];        // weights [n][k]
__device__ __nv_bfloat16 g_Blo[4 * Dc * Dc];
__device__ __nv_bfloat16 g_QKVhi[3 * M_PROJ * Dc];
__device__ __nv_bfloat16 g_QKVlo[3 * M_PROJ * Dc];
__device__ __nv_bfloat16 g_Chi[M_OUT * Dc];
__device__ __nv_bfloat16 g_Clo[M_OUT * Dc];

// ---------------------------------------------------------------------------
__device__ __forceinline__ void split_bf16(float v, __nv_bfloat16& hi, __nv_bfloat16& lo)
{
    hi = __float2bfloat16(v);
    lo = __float2bfloat16(v - __bfloat162float(hi));
}

__global__ void split_a_kernel(const float* __restrict__ s0, const float* __restrict__ s1,
                               const float* __restrict__ s2,
                               __nv_bfloat16* __restrict__ hi, __nv_bfloat16* __restrict__ lo)
{
    int z = blockIdx.z;
    const float* src = (z == 0) ? s0 : (z == 1) ? s1 : s2;
    long long base = (long long)z * M_PROJ * Dc;
    long long n4 = (long long)M_PROJ * Dc / 4;
    long long idx = (long long)blockIdx.x * blockDim.x + threadIdx.x;
    long long stride = (long long)gridDim.x * blockDim.x;
    for (long long i = idx; i < n4; i += stride) {
        float4 v = ((const float4*)src)[i];
        __nv_bfloat16 h[4], l[4];
        split_bf16(v.x, h[0], l[0]);
        split_bf16(v.y, h[1], l[1]);
        split_bf16(v.z, h[2], l[2]);
        split_bf16(v.w, h[3], l[3]);
        long long o = base + i * 4;
        *(__nv_bfloat162*)&hi[o]     = __nv_bfloat162(h[0], h[1]);
        *(__nv_bfloat162*)&hi[o + 2] = __nv_bfloat162(h[2], h[3]);
        *(__nv_bfloat162*)&lo[o]     = __nv_bfloat162(l[0], l[1]);
        *(__nv_bfloat162*)&lo[o + 2] = __nv_bfloat162(l[2], l[3]);
    }
}

__global__ void split_b_kernel(const float* __restrict__ w0, const float* __restrict__ w1,
                               const float* __restrict__ w2, const float* __restrict__ w3,
                               __nv_bfloat16* __restrict__ hi, __nv_bfloat16* __restrict__ lo)
{
    __shared__ float t[32][33];
    int z = blockIdx.z;
    const float* W = (z == 0) ? w0 : (z == 1) ? w1 : (z == 2) ? w2 : w3;
    long long base = (long long)z * Dc * Dc;
    int n0 = blockIdx.x * 32;
    int k0 = blockIdx.y * 32;
    int tx = threadIdx.x, ty = threadIdx.y;
#pragma unroll
    for (int i = 0; i < 4; i++)
        t[ty + i * 8][tx] = W[(long long)(k0 + ty + i * 8) * Dc + n0 + tx];
    __syncthreads();
#pragma unroll
    for (int i = 0; i < 4; i++) {
        float v = t[tx][ty + i * 8];
        long long o = base + (long long)(n0 + ty + i * 8) * Dc + k0 + tx;
        __nv_bfloat16 h, l;
        split_bf16(v, h, l);
        hi[o] = h;
        lo[o] = l;
    }
}

// ---------------------------------------------------------------------------
// mma / ldmatrix helpers
// ---------------------------------------------------------------------------
__device__ __forceinline__ void mma_bf16(float* d, const unsigned* a, const unsigned* b)
{
    asm volatile(
        "mma.sync.aligned.m16n8k16.row.col.f32.bf16.bf16.f32 "
        "{%0,%1,%2,%3}, {%4,%5,%6,%7}, {%8,%9}, {%0,%1,%2,%3};"
        : "+f"(d[0]), "+f"(d[1]), "+f"(d[2]), "+f"(d[3])
        : "r"(a[0]), "r"(a[1]), "r"(a[2]), "r"(a[3]), "r"(b[0]), "r"(b[1]));
}

__device__ __forceinline__ void ldmatrix_x4(unsigned* r, unsigned addr)
{
    asm volatile("ldmatrix.sync.aligned.m8n8.x4.shared.b16 {%0,%1,%2,%3}, [%4];"
        : "=r"(r[0]), "=r"(r[1]), "=r"(r[2]), "=r"(r[3]) : "r"(addr));
}

__device__ __forceinline__ void ldmatrix_x4_trans(unsigned* r, unsigned addr)
{
    asm volatile("ldmatrix.sync.aligned.m8n8.x4.trans.shared.b16 {%0,%1,%2,%3}, [%4];"
        : "=r"(r[0]), "=r"(r[1]), "=r"(r[2]), "=r"(r[3]) : "r"(addr));
}

__device__ __forceinline__ void cpasync16(void* dst_sh, const void* src)
{
    unsigned sh = (unsigned)__cvta_generic_to_shared(dst_sh);
    asm volatile("cp.async.cg.shared.global [%0], [%1], 16;\n" :: "r"(sh), "l"(src));
}

// ---------------------------------------------------------------------------
// bf16-split GEMM with ldmatrix fragment loads (round-10, unchanged).
// ---------------------------------------------------------------------------
#define GS_STRIDE 40
#define GS_TILE   (128 * GS_STRIDE)
#define GS_STAGE  (4 * GS_TILE)
#define GEMM_SMEM_BYTES (2 * GS_STAGE * 2)   // 81920

__global__ __launch_bounds__(256)
void gemm_split_kernel(const __nv_bfloat16* __restrict__ Ah, const __nv_bfloat16* __restrict__ Al,
                       long long aStrideZ,
                       const __nv_bfloat16* __restrict__ Bh, const __nv_bfloat16* __restrict__ Bl,
                       long long bStrideZ,
                       float* C, __nv_bfloat16* Chi, __nv_bfloat16* Clo, long long cStrideZ,
                       const float* b0, const float* b1, const float* b2,
                       int M)
{
    extern __shared__ __nv_bfloat16 smem[];
    unsigned smem_u32 = (unsigned)__cvta_generic_to_shared(smem);
    int z = blockIdx.z;
    Ah += (long long)z * aStrideZ;
    Al += (long long)z * aStrideZ;
    Bh += (long long)z * bStrideZ;
    Bl += (long long)z * bStrideZ;
    const float* bias = (z == 0) ? b0 : (z == 1) ? b1 : b2;

    int tid  = threadIdx.x;
    int lane = tid & 31;
    int warp = tid >> 5;
    int wm = (warp & 1) * 64;
    int wn = (warp >> 1) * 32;
    int row0 = blockIdx.y * 128;
    int col0 = blockIdx.x * 128;

    int cp_arr[8], cp_row[8], cp_c[8];
#pragma unroll
    for (int i = 0; i < 8; i++) {
        cp_arr[i] = i >> 1;
        int idx2 = ((i & 1) << 8) + tid;
        cp_row[i] = idx2 >> 2;
        cp_c[i] = (idx2 & 3) * 8;
    }

    float acc[4][4][4];
#pragma unroll
    for (int im = 0; im < 4; im++)
#pragma unroll
        for (int in_ = 0; in_ < 4; in_++)
#pragma unroll
            for (int r = 0; r < 4; r++) acc[im][in_][r] = 0.f;

    const int nIt = Dc / 32;

    auto load_stage = [&](int it, int s) {
        __nv_bfloat16* st = smem + s * GS_STAGE;
        int k0 = it * 32;
#pragma unroll
        for (int i = 0; i < 8; i++) {
            const __nv_bfloat16* src;
            int row = cp_row[i];
            int c = cp_c[i];
            if (cp_arr[i] == 0)      src = Ah + (long long)(row0 + row) * Dc + k0 + c;
            else if (cp_arr[i] == 1) src = Al + (long long)(row0 + row) * Dc + k0 + c;
            else if (cp_arr[i] == 2) src = Bh + (long long)(col0 + row) * Dc + k0 + c;
            else                     src = Bl + (long long)(col0 + row) * Dc + k0 + c;
            cpasync16(st + cp_arr[i] * GS_TILE + row * GS_STRIDE + c, src);
        }
        asm volatile("cp.async.commit_group;\n" ::);
    };

    load_stage(0, 0);

    for (int it = 0; it < nIt; it++) {
        int buf = it & 1;
        if (it + 1 < nIt) {
            load_stage(it + 1, buf ^ 1);
            asm volatile("cp.async.wait_group 1;\n" ::);
        } else {
            asm volatile("cp.async.wait_group 0;\n" ::);
        }
        __syncthreads();

        unsigned stage_base = smem_u32 + (unsigned)(buf * GS_STAGE * 2);
        unsigned uAh = stage_base;
        unsigned uAl = stage_base + GS_TILE * 2;
        unsigned uBh = stage_base + 2 * GS_TILE * 2;
        unsigned uBl = stage_base + 3 * GS_TILE * 2;

#pragma unroll
        for (int kk = 0; kk < 32; kk += 16) {
            unsigned a_h[4][4], a_l[4][4];
#pragma unroll
            for (int im = 0; im < 4; im++) {
                int row = wm + im * 16 + (lane & 15);
                int col = kk + 8 * (lane >> 4);
                unsigned off = (unsigned)(row * GS_STRIDE + col) * 2;
                ldmatrix_x4(a_h[im], uAh + off);
                ldmatrix_x4(a_l[im], uAl + off);
            }
            unsigned b_h[4][2], b_l[4][2];
#pragma unroll
            for (int nt = 0; nt < 2; nt++) {
                int row = wn + nt * 16 + (lane & 7) + 8 * (lane >> 4);
                int col = kk + 8 * ((lane >> 3) & 1);
                unsigned off = (unsigned)(row * GS_STRIDE + col) * 2;
                unsigned th[4], tl[4];
                ldmatrix_x4(th, uBh + off);
                ldmatrix_x4(tl, uBl + off);
                b_h[2*nt][0] = th[0];   b_h[2*nt][1] = th[1];
                b_h[2*nt+1][0] = th[2]; b_h[2*nt+1][1] = th[3];
                b_l[2*nt][0] = tl[0];   b_l[2*nt][1] = tl[1];
                b_l[2*nt+1][0] = tl[2]; b_l[2*nt+1][1] = tl[3];
            }
#pragma unroll
            for (int im = 0; im < 4; im++)
#pragma unroll
                for (int in_ = 0; in_ < 4; in_++) {
                    mma_bf16(acc[im][in_], a_h[im], b_h[in_]);
                    mma_bf16(acc[im][in_], a_h[im], b_l[in_]);
                    mma_bf16(acc[im][in_], a_l[im], b_h[in_]);
                }
        }
        __syncthreads();
    }

#pragma unroll
    for (int im = 0; im < 4; im++) {
#pragma unroll
        for (int in_ = 0; in_ < 4; in_++) {
            int row = row0 + wm + im * 16 + (lane >> 2);
            int col = col0 + wn + in_ * 8 + 2 * (lane & 3);
            float2 bv = *(const float2*)&bias[col];
            float o0 = acc[im][in_][0] + bv.x, o1 = acc[im][in_][1] + bv.y;
            float o2 = acc[im][in_][2] + bv.x, o3 = acc[im][in_][3] + bv.y;
            long long cb = (long long)z * cStrideZ;
            if (C) {
                *(float2*)&C[cb + (long long)row * Dc + col]       = make_float2(o0, o1);
                *(float2*)&C[cb + (long long)(row + 8) * Dc + col] = make_float2(o2, o3);
            } else {
                __nv_bfloat16 h0, l0, h1, l1, h2, l2, h3, l3;
                split_bf16(o0, h0, l0); split_bf16(o1, h1, l1);
                split_bf16(o2, h2, l2); split_bf16(o3, h3, l3);
                *(__nv_bfloat162*)&Chi[cb + (long long)row * Dc + col]       = __nv_bfloat162(h0, h1);
                *(__nv_bfloat162*)&Clo[cb + (long long)row * Dc + col]       = __nv_bfloat162(l0, l1);
                *(__nv_bfloat162*)&Chi[cb + (long long)(row + 8) * Dc + col] = __nv_bfloat162(h2, h3);
                *(__nv_bfloat162*)&Clo[cb + (long long)(row + 8) * Dc + col] = __nv_bfloat162(l2, l3);
            }
        }
    }
}

// ---------------------------------------------------------------------------
// Tensor-core banded attention, 92.4KB smem -> 2 CTAs/SM.
// Phase aliasing:
//   region1 [0, 55296):      Q/K hi+lo  ->  P hi/lo (after S-mma sync)
//   region2 [55296, 92160):  S fp32     ->  V hi/lo (after A-write sync)
//   [92160, 92416): sinv
// ---------------------------------------------------------------------------
#define AT_STRIDE 72
#define AS_STRIDE 132
#define AP_STRIDE 136
#define O_QH 0
#define O_QL 9216
#define O_KH 18432
#define O_KL 36864
#define O_PH 0
#define O_PL 17408
#define O_SS 55296
#define O_VH 55296
#define O_VL 73728
#define O_SINV 92160
#define ATTN_SMEM_BYTES 92416

__global__ __launch_bounds__(256, 2)
void attn_mma_kernel(const __nv_bfloat16* __restrict__ QKVhi,
                     const __nv_bfloat16* __restrict__ QKVlo,
                     __nv_bfloat16* __restrict__ Chi, __nv_bfloat16* __restrict__ Clo,
                     float* __restrict__ A1, float* __restrict__ A2)
{
    extern __shared__ char smraw[];
    __nv_bfloat16* sQh = (__nv_bfloat16*)(smraw + O_QH);
    __nv_bfloat16* sQl = (__nv_bfloat16*)(smraw + O_QL);
    __nv_bfloat16* sKh = (__nv_bfloat16*)(smraw + O_KH);
    __nv_bfloat16* sKl = (__nv_bfloat16*)(smraw + O_KL);
    float*         sS  = (float*)(smraw + O_SS);
    __nv_bfloat16* sPh = (__nv_bfloat16*)(smraw + O_PH);
    __nv_bfloat16* sPl = (__nv_bfloat16*)(smraw + O_PL);
    __nv_bfloat16* sVh = (__nv_bfloat16*)(smraw + O_VH);
    __nv_bfloat16* sVl = (__nv_bfloat16*)(smraw + O_VL);
    float*         sinv = (float*)(smraw + O_SINV);
    unsigned smem_u32 = (unsigned)__cvta_generic_to_shared(smraw);

    int tid  = threadIdx.x;
    int lane = tid & 31;
    int warp = tid >> 5;
    int q0 = blockIdx.x * 64;
    int h  = blockIdx.y;
    int zz = blockIdx.z;
    int b  = zz >> 1;
    int which = zz & 1;
    int k0 = q0 - HALFW;
    const float scale = 0.125f;

    const long long plane = (long long)M_PROJ * Dc;
    const __nv_bfloat16 *Qh, *Ql, *Kh, *Kl, *Vh, *Vl;
    int rowOffset;
    float* Aout;
    if (which == 0) {
        Qh = QKVhi;           Ql = QKVlo;
        Kh = QKVhi + plane;   Kl = QKVlo + plane;
        Vh = QKVhi + 2*plane; Vl = QKVlo + 2*plane;
        rowOffset = 0;  Aout = A1;
    } else {
        Qh = QKVhi + plane;   Ql = QKVlo + plane;
        Kh = QKVhi;           Kl = QKVlo;
        Vh = QKVhi;           Vl = QKVlo;
        rowOffset = Pc; Aout = A2;
    }
    long long headBase = (long long)b * Pc * Dc + (long long)h * DKc;
    const uint4 zero4 = make_uint4(0, 0, 0, 0);

    // Q tile (64 x 64)
    for (int t = tid; t < 512; t += 256) {
        int r = t >> 3, c = (t & 7) * 8;
        long long src = headBase + (long long)(q0 + r) * Dc + c;
        *(uint4*)&sQh[r * AT_STRIDE + c] = *(const uint4*)&Qh[src];
        *(uint4*)&sQl[r * AT_STRIDE + c] = *(const uint4*)&Ql[src];
    }
    // K tile (128 x 64), zero-padded edges (V deferred until after A-write)
    for (int t = tid; t < 1024; t += 256) {
        int r = t >> 3, c = (t & 7) * 8;
        int j = k0 + r;
        uint4 kh = zero4, kl = zero4;
        if (j >= 0 && j < Pc) {
            long long src = headBase + (long long)j * Dc + c;
            kh = *(const uint4*)&Kh[src];
            kl = *(const uint4*)&Kl[src];
        }
        *(uint4*)&sKh[r * AT_STRIDE + c] = kh;
        *(uint4*)&sKl[r * AT_STRIDE + c] = kl;
    }
    __syncthreads();

    int m0 = (warp & 1) * 32;

    // ---- S = Q*K^T (m32 x n32 per warp, k64), ldmatrix fragments ----
    {
        int n0w = (warp >> 1) * 32;
        float sacc[2][4][4];
#pragma unroll
        for (int mi = 0; mi < 2; mi++)
#pragma unroll
            for (int ni = 0; ni < 4; ni++)
#pragma unroll
                for (int r = 0; r < 4; r++) sacc[mi][ni][r] = 0.f;

#pragma unroll
        for (int ks = 0; ks < 4; ks++) {
            int kc = ks * 16;
            unsigned ah[2][4], al[2][4];
#pragma unroll
            for (int mi = 0; mi < 2; mi++) {
                int row = m0 + mi * 16 + (lane & 15);
                int col = kc + 8 * (lane >> 4);
                unsigned off = (unsigned)(row * AT_STRIDE + col) * 2;
                ldmatrix_x4(ah[mi], smem_u32 + O_QH + off);
                ldmatrix_x4(al[mi], smem_u32 + O_QL + off);
            }
            unsigned bh[4][2], bl[4][2];
#pragma unroll
            for (int nt = 0; nt < 2; nt++) {
                int row = n0w + nt * 16 + (lane & 7) + 8 * (lane >> 4);
                int col = kc + 8 * ((lane >> 3) & 1);
                unsigned off = (unsigned)(row * AT_STRIDE + col) * 2;
                unsigned th[4], tl[4];
                ldmatrix_x4(th, smem_u32 + O_KH + off);
                ldmatrix_x4(tl, smem_u32 + O_KL + off);
                bh[2*nt][0] = th[0]; bh[2*nt][1] = th[1];
                bh[2*nt+1][0] = th[2]; bh[2*nt+1][1] = th[3];
                bl[2*nt][0] = tl[0]; bl[2*nt][1] = tl[1];
                bl[2*nt+1][0] = tl[2]; bl[2*nt+1][1] = tl[3];
            }
#pragma unroll
            for (int mi = 0; mi < 2; mi++)
#pragma unroll
                for (int ni = 0; ni < 4; ni++) {
                    mma_bf16(sacc[mi][ni], ah[mi], bh[ni]);
                    mma_bf16(sacc[mi][ni], ah[mi], bl[ni]);
                    mma_bf16(sacc[mi][ni], al[mi], bh[ni]);
                }
        }
        // write S to smem fp32 (separate region, no alias conflict)
#pragma unroll
        for (int mi = 0; mi < 2; mi++)
#pragma unroll
            for (int ni = 0; ni < 4; ni++) {
                int r = m0 + mi * 16 + (lane >> 2);
                int cc = n0w + ni * 8 + 2 * (lane & 3);
                *(float2*)&sS[r * AS_STRIDE + cc] =
                    make_float2(sacc[mi][ni][0], sacc[mi][ni][1]);
                *(float2*)&sS[(r + 8) * AS_STRIDE + cc] =
                    make_float2(sacc[mi][ni][2], sacc[mi][ni][3]);
            }
    }
    __syncthreads();   // Q/K reads done -> P may alias region1

    // ---- softmax (fp32): unnormalized p -> sS, bf16 hi/lo -> sPh/sPl ----
    {
        int qi = tid >> 2;
        int p  = tid & 3;
        int i_glob = q0 + qi;
        int jlo = i_glob - HALFW; if (jlo < 0) jlo = 0;
        int jhi = i_glob + HALFW; if (jhi > Pc - 1) jhi = Pc - 1;
        int kjlo = jlo - k0;
        int kjhi = jhi - k0;
        float* srow = &sS[qi * AS_STRIDE];
        float m = -1e30f;
#pragma unroll 8
        for (int t = 0; t < 32; t++) {
            int kj = p + 4 * t;
            if (kj >= kjlo && kj <= kjhi) m = fmaxf(m, srow[kj]);
        }
        m = fmaxf(m, __shfl_xor_sync(0xffffffffu, m, 1));
        m = fmaxf(m, __shfl_xor_sync(0xffffffffu, m, 2));
        float sum = 0.f;
#pragma unroll 8
        for (int t = 0; t < 32; t++) {
            int kj = p + 4 * t;
            float pv = 0.f;
            if (kj >= kjlo && kj <= kjhi) {
                pv = __expf(scale * (srow[kj] - m));
                sum += pv;
            }
            srow[kj] = pv;
            __nv_bfloat16 hh, ll;
            split_bf16(pv, hh, ll);
            sPh[qi * AP_STRIDE + kj] = hh;
            sPl[qi * AP_STRIDE + kj] = ll;
        }
        sum += __shfl_xor_sync(0xffffffffu, sum, 1);
        sum += __shfl_xor_sync(0xffffffffu, sum, 2);
        if (p == 0) sinv[qi] = 1.0f / sum;
    }
    __syncthreads();

    // ---- fused dense A write (coalesced rows, streaming stores, fp32 src) ----
    if (Aout) {
        int j0 = tid * 4;
        long long abase = ((long long)b * Hc + h) * Pc * (long long)Pc;
#pragma unroll 2
        for (int r = 0; r < 64; r++) {
            int i_glob = q0 + r;
            int jlo = i_glob - HALFW; if (jlo < 0) jlo = 0;
            int jhi = i_glob + HALFW; if (jhi > Pc - 1) jhi = Pc - 1;
            float inv = sinv[r];
            const float* srow = &sS[r * AS_STRIDE];
            float4 v = make_float4(0.f, 0.f, 0.f, 0.f);
            if (j0 + 3 >= jlo && j0 <= jhi) {
                int j;
                j = j0 + 0; if (j >= jlo && j <= jhi) v.x = srow[j - k0] * inv;
                j = j0 + 1; if (j >= jlo && j <= jhi) v.y = srow[j - k0] * inv;
                j = j0 + 2; if (j >= jlo && j <= jhi) v.z = srow[j - k0] * inv;
                j = j0 + 3; if (j >= jlo && j <= jhi) v.w = srow[j - k0] * inv;
            }
            __stcs((float4*)&Aout[abase + (long long)i_glob * Pc + j0], v);
        }
    }
    __syncthreads();   // S reads done -> V may alias region2

    // ---- V load (128 x 64, row-major) over dead S region ----
    for (int t = tid; t < 1024; t += 256) {
        int r = t >> 3, c = (t & 7) * 8;
        int j = k0 + r;
        uint4 vh = zero4, vl = zero4;
        if (j >= 0 && j < Pc) {
            long long src = headBase + (long long)j * Dc + c;
            vh = *(const uint4*)&Vh[src];
            vl = *(const uint4*)&Vl[src];
        }
        *(uint4*)&sVh[r * AT_STRIDE + c] = vh;
        *(uint4*)&sVl[r * AT_STRIDE + c] = vl;
    }
    __syncthreads();

    // ---- O = P*V (m32 x n16 per warp, k128), ldmatrix P + ldmatrix-trans V ----
    {
        int n0o = (warp >> 1) * 16;
        float oacc[2][2][4];
#pragma unroll
        for (int mi = 0; mi < 2; mi++)
#pragma unroll
            for (int ni = 0; ni < 2; ni++)
#pragma unroll
                for (int r = 0; r < 4; r++) oacc[mi][ni][r] = 0.f;

#pragma unroll
        for (int ks = 0; ks < 8; ks++) {
            int kc = ks * 16;
            unsigned ah[2][4], al[2][4];
#pragma unroll
            for (int mi = 0; mi < 2; mi++) {
                int row = m0 + mi * 16 + (lane & 15);
                int col = kc + 8 * (lane >> 4);
                unsigned off = (unsigned)(row * AP_STRIDE + col) * 2;
                ldmatrix_x4(ah[mi], smem_u32 + O_PH + off);
                ldmatrix_x4(al[mi], smem_u32 + O_PL + off);
            }
            unsigned bh[2][2], bl[2][2];
            {
                int row = kc + (lane & 15);
                int col = n0o + 8 * (lane >> 4);
                unsigned off = (unsigned)(row * AT_STRIDE + col) * 2;
                unsigned th[4], tl[4];
                ldmatrix_x4_trans(th, smem_u32 + O_VH + off);
                ldmatrix_x4_trans(tl, smem_u32 + O_VL + off);
                bh[0][0] = th[0]; bh[0][1] = th[1];
                bh[1][0] = th[2]; bh[1][1] = th[3];
                bl[0][0] = tl[0]; bl[0][1] = tl[1];
                bl[1][0] = tl[2]; bl[1][1] = tl[3];
            }
#pragma unroll
            for (int mi = 0; mi < 2; mi++)
#pragma unroll
                for (int ni = 0; ni < 2; ni++) {
                    mma_bf16(oacc[mi][ni], ah[mi], bh[ni]);
                    mma_bf16(oacc[mi][ni], ah[mi], bl[ni]);
                    mma_bf16(oacc[mi][ni], al[mi], bh[ni]);
                }
        }

#pragma unroll
        for (int mi = 0; mi < 2; mi++)
#pragma unroll
            for (int ni = 0; ni < 2; ni++) {
                int qi0 = m0 + mi * 16 + (lane >> 2);
                int d   = n0o + ni * 8 + 2 * (lane & 3);
                float inv0 = sinv[qi0];
                float inv1 = sinv[qi0 + 8];
                float o0 = oacc[mi][ni][0] * inv0, o1 = oacc[mi][ni][1] * inv0;
                float o2 = oacc[mi][ni][2] * inv1, o3 = oacc[mi][ni][3] * inv1;
                long long dst0 = ((long long)b * CONCAT_P + rowOffset + q0 + qi0) * Dc
                                 + h * DKc + d;
                long long dst1 = dst0 + 8LL * Dc;
                __nv_bfloat16 h0, l0, h1, l1, h2, l2, h3, l3;
                split_bf16(o0, h0, l0); split_bf16(o1, h1, l1);
                split_bf16(o2, h2, l2); split_bf16(o3, h3, l3);
                *(__nv_bfloat162*)&Chi[dst0] = __nv_bfloat162(h0, h1);
                *(__nv_bfloat162*)&Clo[dst0] = __nv_bfloat162(l0, l1);
                *(__nv_bfloat162*)&Chi[dst1] = __nv_bfloat162(h2, h3);
                *(__nv_bfloat162*)&Clo[dst1] = __nv_bfloat162(l2, l3);
            }
    }
}

// ---------------------------------------------------------------------------
extern "C" void kernel_launch(void* const* d_in, const int* in_sizes, int n_in,
                              void* d_out, int out_size)
{
    const float* queries = (const float*)d_in[0];
    const float* keys    = (const float*)d_in[1];
    const float* values  = (const float*)d_in[2];
    const float* Wq = (const float*)d_in[3];
    const float* bq = (const float*)d_in[4];
    const float* Wk = (const float*)d_in[5];
    const float* bk = (const float*)d_in[6];
    const float* Wv = (const float*)d_in[7];
    const float* bv = (const float*)d_in[8];
    const float* Wo = (const float*)d_in[9];
    const float* bo = (const float*)d_in[10];

    float* out = (float*)d_out;

    __nv_bfloat16 *Ahi, *Alo, *Bhi, *Blo, *QKVhi, *QKVlo, *Chi, *Clo;
    cudaGetSymbolAddress((void**)&Ahi, g_Ahi);
    cudaGetSymbolAddress((void**)&Alo, g_Alo);
    cudaGetSymbolAddress((void**)&Bhi, g_Bhi);
    cudaGetSymbolAddress((void**)&Blo, g_Blo);
    cudaGetSymbolAddress((void**)&QKVhi, g_QKVhi);
    cudaGetSymbolAddress((void**)&QKVlo, g_QKVlo);
    cudaGetSymbolAddress((void**)&Chi, g_Chi);
    cudaGetSymbolAddress((void**)&Clo, g_Clo);

    static int attr_set = 0;
    if (!attr_set) {
        cudaFuncSetAttribute(attn_mma_kernel,
                             cudaFuncAttributeMaxDynamicSharedMemorySize, ATTN_SMEM_BYTES);
        cudaFuncSetAttribute(gemm_split_kernel,
                             cudaFuncAttributeMaxDynamicSharedMemorySize, GEMM_SMEM_BYTES);
        attr_set = 1;
    }

    const long long mainN = (long long)M_OUT * Dc;
    const long long aN    = (long long)Bc * Hc * Pc * Pc;
    float* A1 = nullptr;
    float* A2 = nullptr;
    if ((long long)out_size >= mainN + 2 * aN) {
        A1 = out + mainN;
        A2 = A1 + aN;
    }

    split_a_kernel<<<dim3(256, 1, 3), 256>>>(queries, keys, values, Ahi, Alo);
    split_b_kernel<<<dim3(16, 16, 4), dim3(32, 8)>>>(Wq, Wk, Wv, Wo, Bhi, Blo);

    const long long aStride = (long long)M_PROJ * Dc;
    const long long bStride = (long long)Dc * Dc;

    gemm_split_kernel<<<dim3(Dc / 128, M_PROJ / 128, 3), 256, GEMM_SMEM_BYTES>>>(
        Ahi, Alo, aStride, Bhi, Blo, bStride,
        nullptr, QKVhi, QKVlo, aStride, bq, bk, bv, M_PROJ);

    dim3 ga(Pc / 64, Hc, Bc * 2);
    attn_mma_kernel<<<ga, 256, ATTN_SMEM_BYTES>>>(QKVhi, QKVlo, Chi, Clo, A1, A2);

    gemm_split_kernel<<<dim3(Dc / 128, M_OUT / 128, 1), 256, GEMM_SMEM_BYTES>>>(
        Chi, Clo, 0, Bhi + 3 * bStride, Blo + 3 * bStride, 0,
        out, nullptr, nullptr, 0, bo, bo, bo, M_OUT);
}